// round 11
// baseline (speedup 1.0000x reference)
#include <cuda_runtime.h>
#include <cuda_bf16.h>
#include <cstdint>

// ---------------------------------------------------------------------------
// SchNet interaction block, sm_103 — v11: HMMA K2, 2 atoms per CTA (M=128).
//   prep:  W1^T, W2^T -> pre-swizzled bf16 hi/lo chunk images (prep_w)
//   K1:    XF = x @ W_in2f                         (gemm32, FFMA2)
//   K2:    fused filter MLP + gather + aggregate   (k2_hmma, mma.sync bf16)
//   K3:    ssp((Y@Wf2o+b)@Wd + G@Wang + b)         (tail, FFMA2)
// K2 GEMMs: D += Ahi*Bhi + Ahi*Blo + Alo*Bhi (bf16 splits, fp32 acc).
// v11: 512 threads, 16 warps (4 M-quarters x 4 N-quarters); weights staged
// once per 2 atoms; syncs/waits amortized; 4 warps/SMSP latency hiding.
// ---------------------------------------------------------------------------

#define BDIM  256
#define BDIM2 512
#define NATOMS 4096
#define CUTOFF 5.0f

// K2 smem layout (bytes)
#define SXS        260                 // sX row stride in floats
#define SLOT_OFF   133120              // after sX: 128*260*4
#define BUF_BYTES  16384               // one staged chunk (256 f x 64B)
#define SMEM_M_OFF 165888
#define SMEM_R_OFF 166400
#define SMEM_RED_OFF 166912
#define SMEM_K2_TOTAL 171008

__device__ float g_XF[NATOMS * 256];
__device__ float g_Y [NATOMS * 256];
__device__ __align__(16) uint4 g_w1s[8 * 1024];    // 8 chunks x 256 f x 4 slots
__device__ __align__(16) uint4 g_w2s[16 * 1024];   // 16 chunks

// ================= helpers =================

__device__ __forceinline__ uint32_t smem_u32(const void* p) {
    uint32_t a;
    asm("{ .reg .u64 t; cvta.to.shared.u64 t, %1; cvt.u32.u64 %0, t; }" : "=r"(a) : "l"(p));
    return a;
}
__device__ __forceinline__ float sspf(float v) {
    float e = __expf(v);
    float r = __logf(fmaf(0.5f, e, 0.5f));
    return (v > 60.0f) ? (v - 0.69314718055994531f) : r;
}
__device__ __forceinline__ void fma2(unsigned long long& d, unsigned long long a, unsigned long long b) {
    asm("fma.rn.f32x2 %0, %1, %2, %3;" : "=l"(d) : "l"(a), "l"(b), "l"(d));
}
__device__ __forceinline__ unsigned long long pack_dup(float v) {
    unsigned long long r; asm("mov.b64 %0, {%1, %1};" : "=l"(r) : "f"(v)); return r;
}
__device__ __forceinline__ float2 unpack2(unsigned long long u) {
    float2 r; asm("mov.b64 {%0, %1}, %2;" : "=f"(r.x), "=f"(r.y) : "l"(u)); return r;
}
__device__ __forceinline__ float f4c(const float4& v, int i) {
    return i == 0 ? v.x : i == 1 ? v.y : i == 2 ? v.z : v.w;
}
// pack (v0,v1) -> bf16x2, v0 in LOW half
__device__ __forceinline__ uint32_t pack_bf2(float v0, float v1) {
    uint32_t r;
    asm("cvt.rn.satfinite.bf16x2.f32 %0, %1, %2;" : "=r"(r) : "f"(v1), "f"(v0));
    return r;
}
__device__ __forceinline__ float bf2_lo(uint32_t p) { return __uint_as_float(p << 16); }
__device__ __forceinline__ float bf2_hi(uint32_t p) { return __uint_as_float(p & 0xffff0000u); }

__device__ __forceinline__ void mma_bf16(float* d, uint32_t a0, uint32_t a1, uint32_t a2, uint32_t a3,
                                         uint32_t b0, uint32_t b1) {
    asm volatile("mma.sync.aligned.m16n8k16.row.col.f32.bf16.bf16.f32 "
                 "{%0,%1,%2,%3}, {%4,%5,%6,%7}, {%8,%9}, {%0,%1,%2,%3};"
                 : "+f"(d[0]), "+f"(d[1]), "+f"(d[2]), "+f"(d[3])
                 : "r"(a0), "r"(a1), "r"(a2), "r"(a3), "r"(b0), "r"(b1));
}

__device__ __forceinline__ void cp16(uint32_t dst, const void* src) {
    asm volatile("cp.async.cg.shared.global [%0], [%1], 16;" :: "r"(dst), "l"(src) : "memory");
}
#define CP_COMMIT() asm volatile("cp.async.commit_group;" ::: "memory")
#define CP_WAIT0()  asm volatile("cp.async.wait_group 0;" ::: "memory")

// stage one pre-swizzled 16KB chunk image into a smem slot (512 threads)
__device__ __forceinline__ void stage_w(uint32_t sbase, int buf, const uint4* ws, int s, int tid) {
    uint32_t d = sbase + SLOT_OFF + (uint32_t)buf * BUF_BYTES + (uint32_t)tid * 32;
    const char* g = (const char*)(ws + s * 1024) + tid * 32;
    cp16(d,      g);
    cp16(d + 16, g + 16);
}

// one K=16 step: acc[2][8][4] += A(rows mw*32..+31 of sX) * B(slot cols nb*64..+63)
__device__ __forceinline__ void gemm_kstep(float (&acc)[2][8][4], const float* sX, int k0,
                                           const char* slot, int mw, int nb, int q, int c,
                                           int slSel) {
    uint32_t ah[2][4], al[2][4];
    #pragma unroll
    for (int t = 0; t < 2; ++t) {
        const float* bp = sX + (mw * 32 + t * 16 + q) * SXS + k0 + 2 * c;
        float2 v0 = *(const float2*)(bp);
        float2 v1 = *(const float2*)(bp + 8 * SXS);
        float2 v2 = *(const float2*)(bp + 8);
        float2 v3 = *(const float2*)(bp + 8 * SXS + 8);
        ah[t][0] = pack_bf2(v0.x, v0.y); al[t][0] = pack_bf2(v0.x - bf2_lo(ah[t][0]), v0.y - bf2_hi(ah[t][0]));
        ah[t][1] = pack_bf2(v1.x, v1.y); al[t][1] = pack_bf2(v1.x - bf2_lo(ah[t][1]), v1.y - bf2_hi(ah[t][1]));
        ah[t][2] = pack_bf2(v2.x, v2.y); al[t][2] = pack_bf2(v2.x - bf2_lo(ah[t][2]), v2.y - bf2_hi(ah[t][2]));
        ah[t][3] = pack_bf2(v3.x, v3.y); al[t][3] = pack_bf2(v3.x - bf2_lo(ah[t][3]), v3.y - bf2_hi(ah[t][3]));
    }
    #pragma unroll
    for (int nt = 0; nt < 8; ++nt) {
        const int f = nb * 64 + nt * 8 + q;
        uint4 B = *(const uint4*)(slot + f * 64 + slSel * 16);
        mma_bf16(acc[0][nt], ah[0][0], ah[0][1], ah[0][2], ah[0][3], B.x, B.y);
        mma_bf16(acc[0][nt], ah[0][0], ah[0][1], ah[0][2], ah[0][3], B.z, B.w);
        mma_bf16(acc[0][nt], al[0][0], al[0][1], al[0][2], al[0][3], B.x, B.y);
        mma_bf16(acc[1][nt], ah[1][0], ah[1][1], ah[1][2], ah[1][3], B.x, B.y);
        mma_bf16(acc[1][nt], ah[1][0], ah[1][1], ah[1][2], ah[1][3], B.z, B.w);
        mma_bf16(acc[1][nt], al[1][0], al[1][1], al[1][2], al[1][3], B.x, B.y);
    }
}

// ================= prep: pre-swizzled chunk images =================

__global__ void prep_w(const float* __restrict__ W1, const float* __restrict__ W2,
                       uint4* __restrict__ w1s, uint4* __restrict__ w2s)
{
    int i = blockIdx.x * 256 + threadIdx.x;   // 24576 total
    const float* W; uint4* dst; int idx;
    if (i < 8192) { W = W1; dst = w1s; idx = i; }
    else          { W = W2; dst = w2s; idx = i - 8192; }
    const int s = idx >> 10;
    const int r = idx & 1023;
    const int f = r >> 2;
    const int slotIdx = r & 3;
    const int c = (slotIdx - (f >> 1)) & 3;
    const int k0 = s * 16 + 2 * c;
    float v0 = W[(size_t)(k0)     * 256 + f];
    float v1 = W[(size_t)(k0 + 1) * 256 + f];
    float v2 = W[(size_t)(k0 + 8) * 256 + f];
    float v3 = W[(size_t)(k0 + 9) * 256 + f];
    uint32_t h0 = pack_bf2(v0, v1);
    uint32_t h1 = pack_bf2(v2, v3);
    uint32_t l0 = pack_bf2(v0 - bf2_lo(h0), v1 - bf2_hi(h0));
    uint32_t l1 = pack_bf2(v2 - bf2_lo(h1), v3 - bf2_hi(h1));
    dst[s * 1024 + f * 4 + slotIdx] = make_uint4(h0, h1, l0, l1);
}

// ================= K2: HMMA fused filter (1 CTA = 2 atoms) =================

__global__ __launch_bounds__(BDIM2)
void k2_hmma(const float* __restrict__ f_ij, const float* __restrict__ r_ij,
             const float* __restrict__ nmask, const int* __restrict__ neigh,
             const uint4* __restrict__ w1s, const uint4* __restrict__ w2s,
             const float* __restrict__ b1, const float* __restrict__ b2,
             const float* __restrict__ XF, float* __restrict__ Y)
{
    extern __shared__ char smc[];
    float* sX   = (float*)smc;
    float* sM   = (float*)(smc + SMEM_M_OFF);
    int*   sRow = (int*)  (smc + SMEM_R_OFF);
    float* sRed = (float*)(smc + SMEM_RED_OFF);   // [4][256]
    const uint32_t sbase = smem_u32(smc);
    const int tid = threadIdx.x, wid = tid >> 5, lane = tid & 31;
    const int q = lane >> 2, c = lane & 3;
    const int slSel = (c + (q >> 1)) & 3;
    const int mw = wid & 3, nb = wid >> 2;
    const int bid = blockIdx.x;

    // kick off W1 chunk 0 immediately
    stage_w(sbase, 0, w1s, 0, tid);
    CP_COMMIT();

    // F [128 rows][128 cols] fp32 -> sX (stride SXS); rows 0..63 atom0, 64..127 atom1
    {
        const float4* f4 = (const float4*)(f_ij + (size_t)bid * 16384);
        #pragma unroll
        for (int u = 0; u < 8; ++u) {
            int i4 = tid + u * 512;
            int row = i4 >> 5, c4 = i4 & 31;
            *(float4*)(sX + row * SXS + c4 * 4) = f4[i4];
        }
    }
    if (tid < 128) {
        int ga = 2 * bid + (tid >> 6);
        int nn = tid & 63;
        float r = r_ij[ga * 64 + nn];
        float m = nmask[ga * 64 + nn];
        sM[tid]   = (r <= CUTOFF) ? m : 0.0f;
        sRow[tid] = (ga >> 9) * 512 + neigh[ga * 64 + nn];
    }

    float acc[2][8][4];
    #pragma unroll
    for (int a = 0; a < 2; ++a)
        #pragma unroll
        for (int n = 0; n < 8; ++n)
            #pragma unroll
            for (int i = 0; i < 4; ++i) acc[a][n][i] = 0.0f;

    // ---- GEMM1: P = F @ W1 (K=128, 8 ksteps) ----
    #pragma unroll 1
    for (int s = 0; s < 8; ++s) {
        CP_WAIT0();
        __syncthreads();
        if (s < 7) { stage_w(sbase, (s + 1) & 1, w1s, s + 1, tid); CP_COMMIT(); }
        gemm_kstep(acc, sX, s * 16, smc + SLOT_OFF + (s & 1) * BUF_BYTES, mw, nb, q, c, slSel);
    }
    __syncthreads();   // all warps done reading F region

    // kick off W2 chunk 0 while doing the H epilogue
    stage_w(sbase, 0, w2s, 0, tid);
    CP_COMMIT();

    // ---- H = ssp(P + b1) -> sX cols 0..255 ----
    #pragma unroll
    for (int nt = 0; nt < 8; ++nt) {
        const int col = nb * 64 + nt * 8 + 2 * c;
        float2 bv = *(const float2*)(b1 + col);
        #pragma unroll
        for (int t = 0; t < 2; ++t) {
            const int r0 = mw * 32 + t * 16 + q;
            *(float2*)(sX + r0 * SXS + col) =
                make_float2(sspf(acc[t][nt][0] + bv.x), sspf(acc[t][nt][1] + bv.y));
            *(float2*)(sX + (r0 + 8) * SXS + col) =
                make_float2(sspf(acc[t][nt][2] + bv.x), sspf(acc[t][nt][3] + bv.y));
        }
    }
    #pragma unroll
    for (int a = 0; a < 2; ++a)
        #pragma unroll
        for (int n = 0; n < 8; ++n)
            #pragma unroll
            for (int i = 0; i < 4; ++i) acc[a][n][i] = 0.0f;

    // ---- GEMM2: Wf = H @ W2 (K=256, 16 ksteps) ----
    #pragma unroll 1
    for (int s = 0; s < 16; ++s) {
        CP_WAIT0();
        __syncthreads();
        if (s < 15) { stage_w(sbase, (s + 1) & 1, w2s, s + 1, tid); CP_COMMIT(); }
        gemm_kstep(acc, sX, s * 16, smc + SLOT_OFF + (s & 1) * BUF_BYTES, mw, nb, q, c, slSel);
    }
    __syncthreads();   // all warps done reading H region

    // ---- gather XF rows into sX (coalesced; 16 warps x 8 rows = 128) ----
    #pragma unroll
    for (int rr = 0; rr < 8; ++rr) {
        const int row = wid * 8 + rr;
        const float4* src = (const float4*)(XF + (size_t)sRow[row] * 256);
        *(float4*)(sX + row * SXS + lane * 4)        = src[lane];
        *(float4*)(sX + row * SXS + (lane + 32) * 4) = src[lane + 32];
    }
    __syncthreads();

    // ---- epilogue: per-warp column partials over its 32 rows ----
    #pragma unroll
    for (int nt = 0; nt < 8; ++nt) {
        const int col = nb * 64 + nt * 8 + 2 * c;
        float2 bv = *(const float2*)(b2 + col);
        float pe = 0.0f, po = 0.0f;
        #pragma unroll
        for (int t = 0; t < 2; ++t) {
            #pragma unroll
            for (int p = 0; p < 2; ++p) {
                const int row = mw * 32 + t * 16 + q + 8 * p;
                const float m = sM[row];
                float2 x = *(const float2*)(sX + row * SXS + col);
                pe = fmaf(m * (acc[t][nt][2 * p]     + bv.x), x.x, pe);
                po = fmaf(m * (acc[t][nt][2 * p + 1] + bv.y), x.y, po);
            }
        }
        pe += __shfl_xor_sync(0xffffffffu, pe, 4);
        pe += __shfl_xor_sync(0xffffffffu, pe, 8);
        pe += __shfl_xor_sync(0xffffffffu, pe, 16);
        po += __shfl_xor_sync(0xffffffffu, po, 4);
        po += __shfl_xor_sync(0xffffffffu, po, 8);
        po += __shfl_xor_sync(0xffffffffu, po, 16);
        if (q == nt) {
            sRed[mw * 256 + col]     = pe;
            sRed[mw * 256 + col + 1] = po;
        }
    }
    __syncthreads();
    {   // atom a: rows in mw {2a, 2a+1}
        const int a   = tid >> 8;
        const int col = tid & 255;
        Y[(size_t)(2 * bid + a) * 256 + col] =
            sRed[(2 * a) * 256 + col] + sRed[(2 * a + 1) * 256 + col];
    }
}

// ================= K1 (FFMA2 gemm32) =================

template<int JROWS>
__device__ __forceinline__ void mma_tile8(const float* cur, const float* sA,
                                          int lda, int rowbase, int f0,
                                          unsigned long long (&acc)[JROWS][4])
{
    #pragma unroll
    for (int kq = 0; kq < 8; kq += 4) {
        float4 av[JROWS];
        #pragma unroll
        for (int j = 0; j < JROWS; ++j)
            av[j] = *(const float4*)&sA[(rowbase + j) * lda + kq];
        #pragma unroll
        for (int kk = 0; kk < 4; ++kk) {
            ulonglong2 bva = *(const ulonglong2*)&cur[(kq + kk) * 256 + f0];
            ulonglong2 bvb = *(const ulonglong2*)&cur[(kq + kk) * 256 + f0 + 4];
            #pragma unroll
            for (int j = 0; j < JROWS; ++j) {
                unsigned long long a2 = pack_dup(f4c(av[j], kk));
                fma2(acc[j][0], a2, bva.x);
                fma2(acc[j][1], a2, bva.y);
                fma2(acc[j][2], a2, bvb.x);
                fma2(acc[j][3], a2, bvb.y);
            }
        }
    }
}

__global__ __launch_bounds__(BDIM, 2)
void gemm32_kernel(const float* __restrict__ A, const float* __restrict__ W,
                   float* __restrict__ C)
{
    extern __shared__ float smem[];
    float* sA = smem; float* sWa = smem + 8192; float* sWb = smem + 10240;
    const int tid = threadIdx.x, tn = tid >> 5;
    const int f0 = (tid & 31) * 8, r0 = tn * 4;
    {
        const float* src = A + (size_t)blockIdx.x * 8192;
        #pragma unroll
        for (int u = 0; u < 8; ++u)
            *(float4*)&sA[tid * 4 + u * 1024] = *(const float4*)&src[tid * 4 + u * 1024];
    }
    *(float4*)&sWa[tid * 8]     = *(const float4*)&W[tid * 8];
    *(float4*)&sWa[tid * 8 + 4] = *(const float4*)&W[tid * 8 + 4];
    __syncthreads();
    unsigned long long acc[4][4];
    #pragma unroll
    for (int j = 0; j < 4; ++j) { acc[j][0]=acc[j][1]=acc[j][2]=acc[j][3]=0ull; }
    #pragma unroll 1
    for (int k0 = 0; k0 < 256; k0 += 8) {
        const float* cur = ((k0 >> 3) & 1) ? sWb : sWa;
        float*       nxt = ((k0 >> 3) & 1) ? sWa : sWb;
        float4 p0, p1;
        const bool more = (k0 + 8) < 256;
        if (more) {
            p0 = *(const float4*)&W[(k0 + 8) * 256 + tid * 8];
            p1 = *(const float4*)&W[(k0 + 8) * 256 + tid * 8 + 4];
        }
        mma_tile8<4>(cur, sA + k0, 256, r0, f0, acc);
        if (more) { *(float4*)&nxt[tid * 8] = p0; *(float4*)&nxt[tid * 8 + 4] = p1; }
        __syncthreads();
    }
    #pragma unroll
    for (int j = 0; j < 4; ++j) {
        float w[8];
        #pragma unroll
        for (int i2 = 0; i2 < 4; ++i2) {
            float2 v = unpack2(acc[j][i2]); w[2*i2] = v.x; w[2*i2+1] = v.y;
        }
        const int row = blockIdx.x * 32 + r0 + j;
        *(float4*)&C[(size_t)row * 256 + f0]     = make_float4(w[0], w[1], w[2], w[3]);
        *(float4*)&C[(size_t)row * 256 + f0 + 4] = make_float4(w[4], w[5], w[6], w[7]);
    }
}

// ================= K3 (FFMA2 fused tail) =================

__global__ __launch_bounds__(BDIM, 2)
void tail_kernel(const float* __restrict__ Yin, const float* __restrict__ Gin,
                 const float* __restrict__ W_f2out, const float* __restrict__ b_f2out,
                 const float* __restrict__ W_dense, const float* __restrict__ b_dense,
                 const float* __restrict__ W_ang, float* __restrict__ out)
{
    extern __shared__ float smem[];
    float* sY = smem; float* sT = smem + 8192; float* sG = smem + 16384;
    float* sWa = smem + 20480; float* sWb = smem + 22528;
    const int tid = threadIdx.x, tn = tid >> 5;
    const int f0 = (tid & 31) * 8, r0 = tn * 4;
    {
        const float* src = Yin + (size_t)blockIdx.x * 8192;
        #pragma unroll
        for (int u = 0; u < 8; ++u)
            *(float4*)&sY[tid * 4 + u * 1024] = *(const float4*)&src[tid * 4 + u * 1024];
        const float* srcg = Gin + (size_t)blockIdx.x * 4096;
        #pragma unroll
        for (int u = 0; u < 4; ++u)
            *(float4*)&sG[tid * 4 + u * 1024] = *(const float4*)&srcg[tid * 4 + u * 1024];
    }
    *(float4*)&sWa[tid * 8]     = *(const float4*)&W_f2out[tid * 8];
    *(float4*)&sWa[tid * 8 + 4] = *(const float4*)&W_f2out[tid * 8 + 4];
    __syncthreads();
    unsigned long long acc[4][4];
    #pragma unroll
    for (int j = 0; j < 4; ++j) { acc[j][0]=acc[j][1]=acc[j][2]=acc[j][3]=0ull; }
    #pragma unroll 1
    for (int k0 = 0; k0 < 256; k0 += 8) {
        const float* cur = ((k0 >> 3) & 1) ? sWb : sWa;
        float*       nxt = ((k0 >> 3) & 1) ? sWa : sWb;
        float4 p0, p1;
        const bool more = (k0 + 8) < 256;
        if (more) {
            p0 = *(const float4*)&W_f2out[(k0 + 8) * 256 + tid * 8];
            p1 = *(const float4*)&W_f2out[(k0 + 8) * 256 + tid * 8 + 4];
        }
        mma_tile8<4>(cur, sY + k0, 256, r0, f0, acc);
        if (more) { *(float4*)&nxt[tid * 8] = p0; *(float4*)&nxt[tid * 8 + 4] = p1; }
        __syncthreads();
    }
    {
        float4 ba = *(const float4*)&b_f2out[f0];
        float4 bb4 = *(const float4*)&b_f2out[f0 + 4];
        float bb[8] = {ba.x, ba.y, ba.z, ba.w, bb4.x, bb4.y, bb4.z, bb4.w};
        #pragma unroll
        for (int j = 0; j < 4; ++j) {
            float w[8];
            #pragma unroll
            for (int i2 = 0; i2 < 4; ++i2) {
                float2 v = unpack2(acc[j][i2]);
                w[2*i2] = v.x + bb[2*i2]; w[2*i2+1] = v.y + bb[2*i2+1];
            }
            *(float4*)&sT[(r0 + j) * 256 + f0]     = make_float4(w[0], w[1], w[2], w[3]);
            *(float4*)&sT[(r0 + j) * 256 + f0 + 4] = make_float4(w[4], w[5], w[6], w[7]);
        }
    }
    __syncthreads();
    *(float4*)&sWa[tid * 8]     = *(const float4*)&W_dense[tid * 8];
    *(float4*)&sWa[tid * 8 + 4] = *(const float4*)&W_dense[tid * 8 + 4];
    #pragma unroll
    for (int j = 0; j < 4; ++j) { acc[j][0]=acc[j][1]=acc[j][2]=acc[j][3]=0ull; }
    __syncthreads();
    #pragma unroll 1
    for (int k0 = 0; k0 < 256; k0 += 8) {
        const float* cur = ((k0 >> 3) & 1) ? sWb : sWa;
        float*       nxt = ((k0 >> 3) & 1) ? sWa : sWb;
        float4 p0, p1;
        const bool more = (k0 + 8) < 256;
        if (more) {
            p0 = *(const float4*)&W_dense[(k0 + 8) * 256 + tid * 8];
            p1 = *(const float4*)&W_dense[(k0 + 8) * 256 + tid * 8 + 4];
        } else {
            p0 = *(const float4*)&W_ang[tid * 8];
            p1 = *(const float4*)&W_ang[tid * 8 + 4];
        }
        mma_tile8<4>(cur, sT + k0, 256, r0, f0, acc);
        *(float4*)&nxt[tid * 8] = p0; *(float4*)&nxt[tid * 8 + 4] = p1;
        __syncthreads();
    }
    #pragma unroll 1
    for (int k0 = 0; k0 < 128; k0 += 8) {
        const float* cur = ((k0 >> 3) & 1) ? sWb : sWa;
        float*       nxt = ((k0 >> 3) & 1) ? sWa : sWb;
        float4 p0, p1;
        const bool more = (k0 + 8) < 128;
        if (more) {
            p0 = *(const float4*)&W_ang[(k0 + 8) * 256 + tid * 8];
            p1 = *(const float4*)&W_ang[(k0 + 8) * 256 + tid * 8 + 4];
        }
        mma_tile8<4>(cur, sG + k0, 128, r0, f0, acc);
        if (more) { *(float4*)&nxt[tid * 8] = p0; *(float4*)&nxt[tid * 8 + 4] = p1; }
        __syncthreads();
    }
    {
        float4 ba = *(const float4*)&b_dense[f0];
        float4 bb4 = *(const float4*)&b_dense[f0 + 4];
        float bb[8] = {ba.x, ba.y, ba.z, ba.w, bb4.x, bb4.y, bb4.z, bb4.w};
        #pragma unroll
        for (int j = 0; j < 4; ++j) {
            float w[8];
            #pragma unroll
            for (int i2 = 0; i2 < 4; ++i2) {
                float2 v = unpack2(acc[j][i2]);
                w[2*i2] = sspf(v.x + bb[2*i2]); w[2*i2+1] = sspf(v.y + bb[2*i2+1]);
            }
            const int row = blockIdx.x * 32 + r0 + j;
            *(float4*)&out[(size_t)row * 256 + f0]     = make_float4(w[0], w[1], w[2], w[3]);
            *(float4*)&out[(size_t)row * 256 + f0 + 4] = make_float4(w[4], w[5], w[6], w[7]);
        }
    }
}

// ---------------------------------------------------------------------------

extern "C" void kernel_launch(void* const* d_in, const int* in_sizes, int n_in,
                              void* d_out, int out_size)
{
    const float* x        = (const float*)d_in[0];
    const float* r_ij     = (const float*)d_in[1];
    const float* f_ij     = (const float*)d_in[2];
    const float* G_i      = (const float*)d_in[3];
    const float* nmask    = (const float*)d_in[4];
    const int*   neigh    = (const int*)  d_in[5];
    const float* W_in2f   = (const float*)d_in[6];
    const float* W1       = (const float*)d_in[7];
    const float* b1       = (const float*)d_in[8];
    const float* W2       = (const float*)d_in[9];
    const float* b2       = (const float*)d_in[10];
    const float* W_f2out  = (const float*)d_in[11];
    const float* b_f2out  = (const float*)d_in[12];
    const float* W_dense  = (const float*)d_in[13];
    const float* b_dense  = (const float*)d_in[14];
    const float* W_ang    = (const float*)d_in[15];
    float* out = (float*)d_out;

    float *pXF, *pY;
    uint4 *p1s, *p2s;
    cudaGetSymbolAddress((void**)&pXF, g_XF);
    cudaGetSymbolAddress((void**)&pY,  g_Y);
    cudaGetSymbolAddress((void**)&p1s, g_w1s);
    cudaGetSymbolAddress((void**)&p2s, g_w2s);

    const size_t smem1 = (8192 + 4096) * 4;
    const size_t smem2 = SMEM_K2_TOTAL;
    const size_t smem3 = 24576 * 4;

    cudaFuncSetAttribute(gemm32_kernel, cudaFuncAttributeMaxDynamicSharedMemorySize, (int)smem1);
    cudaFuncSetAttribute(k2_hmma,       cudaFuncAttributeMaxDynamicSharedMemorySize, (int)smem2);
    cudaFuncSetAttribute(tail_kernel,   cudaFuncAttributeMaxDynamicSharedMemorySize, (int)smem3);

    prep_w<<<96, 256>>>(W1, W2, p1s, p2s);
    gemm32_kernel<<<NATOMS / 32, BDIM, smem1>>>(x, W_in2f, pXF);
    k2_hmma<<<NATOMS / 2, BDIM2, smem2>>>(
        f_ij, r_ij, nmask, neigh, p1s, p2s, b1, b2, pXF, pY);
    tail_kernel<<<NATOMS / 32, BDIM, smem3>>>(
        pY, G_i, W_f2out, b_f2out, W_dense, b_dense, W_ang, out);
}

// round 12
// speedup vs baseline: 1.0606x; 1.0606x over previous
#include <cuda_runtime.h>
#include <cuda_bf16.h>
#include <cstdint>

// ---------------------------------------------------------------------------
// SchNet interaction block, sm_103 — v12: v7 K2 (frozen) + 16-row K1/K3 tiles.
//   prep:  W1^T, W2^T -> pre-swizzled bf16 hi/lo chunk images (prep_w)
//   K1:    XF = x @ W_in2f                         (gemm16, FFMA2, grid 256)
//   K2:    fused filter MLP + gather + aggregate   (k2_hmma, mma.sync bf16) = v7
//   K3:    ssp((Y@Wf2o+b)@Wd + G@Wang + b)         (tail16, FFMA2, grid 256)
// v12: K1/K3 tiles halved (32->16 rows) so ~2 CTAs/SM overlap the staging
// and sync phases that left issue at 23% with grid=128.
// ---------------------------------------------------------------------------

#define BDIM 256
#define NATOMS 4096
#define CUTOFF 5.0f

// K2 smem layout (bytes) — identical to v7
#define SXS        260
#define SLOT_OFF   66560
#define BUF_BYTES  16384
#define SMEM_M_OFF 99328
#define SMEM_R_OFF 99584
#define SMEM_RED_OFF 99840
#define SMEM_K2_TOTAL 101888

__device__ float g_XF[NATOMS * 256];
__device__ float g_Y [NATOMS * 256];
__device__ __align__(16) uint4 g_w1s[8 * 1024];
__device__ __align__(16) uint4 g_w2s[16 * 1024];

// ================= helpers =================

__device__ __forceinline__ uint32_t smem_u32(const void* p) {
    uint32_t a;
    asm("{ .reg .u64 t; cvta.to.shared.u64 t, %1; cvt.u32.u64 %0, t; }" : "=r"(a) : "l"(p));
    return a;
}
__device__ __forceinline__ float sspf(float v) {
    float e = __expf(v);
    float r = __logf(fmaf(0.5f, e, 0.5f));
    return (v > 60.0f) ? (v - 0.69314718055994531f) : r;
}
__device__ __forceinline__ void fma2(unsigned long long& d, unsigned long long a, unsigned long long b) {
    asm("fma.rn.f32x2 %0, %1, %2, %3;" : "=l"(d) : "l"(a), "l"(b), "l"(d));
}
__device__ __forceinline__ unsigned long long pack_dup(float v) {
    unsigned long long r; asm("mov.b64 %0, {%1, %1};" : "=l"(r) : "f"(v)); return r;
}
__device__ __forceinline__ float2 unpack2(unsigned long long u) {
    float2 r; asm("mov.b64 {%0, %1}, %2;" : "=f"(r.x), "=f"(r.y) : "l"(u)); return r;
}
__device__ __forceinline__ float f4c(const float4& v, int i) {
    return i == 0 ? v.x : i == 1 ? v.y : i == 2 ? v.z : v.w;
}
__device__ __forceinline__ uint32_t pack_bf2(float v0, float v1) {
    uint32_t r;
    asm("cvt.rn.satfinite.bf16x2.f32 %0, %1, %2;" : "=r"(r) : "f"(v1), "f"(v0));
    return r;
}
__device__ __forceinline__ float bf2_lo(uint32_t p) { return __uint_as_float(p << 16); }
__device__ __forceinline__ float bf2_hi(uint32_t p) { return __uint_as_float(p & 0xffff0000u); }

__device__ __forceinline__ void mma_bf16(float* d, uint32_t a0, uint32_t a1, uint32_t a2, uint32_t a3,
                                         uint32_t b0, uint32_t b1) {
    asm volatile("mma.sync.aligned.m16n8k16.row.col.f32.bf16.bf16.f32 "
                 "{%0,%1,%2,%3}, {%4,%5,%6,%7}, {%8,%9}, {%0,%1,%2,%3};"
                 : "+f"(d[0]), "+f"(d[1]), "+f"(d[2]), "+f"(d[3])
                 : "r"(a0), "r"(a1), "r"(a2), "r"(a3), "r"(b0), "r"(b1));
}

__device__ __forceinline__ void cp16(uint32_t dst, const void* src) {
    asm volatile("cp.async.cg.shared.global [%0], [%1], 16;" :: "r"(dst), "l"(src) : "memory");
}
#define CP_COMMIT() asm volatile("cp.async.commit_group;" ::: "memory")
#define CP_WAIT0()  asm volatile("cp.async.wait_group 0;" ::: "memory")

__device__ __forceinline__ void stage_w(uint32_t sbase, int buf, const uint4* ws, int s, int tid) {
    uint32_t d = sbase + SLOT_OFF + (uint32_t)buf * BUF_BYTES + (uint32_t)tid * 64;
    const char* g = (const char*)(ws + s * 1024) + tid * 64;
    cp16(d,      g);
    cp16(d + 16, g + 16);
    cp16(d + 32, g + 32);
    cp16(d + 48, g + 48);
}

__device__ __forceinline__ void gemm_kstep(float (&acc)[2][8][4], const float* sX, int k0,
                                           const char* slot, int mt, int nb, int q, int c,
                                           int slSel) {
    uint32_t ah[2][4], al[2][4];
    #pragma unroll
    for (int t = 0; t < 2; ++t) {
        const float* bp = sX + (mt * 32 + t * 16 + q) * SXS + k0 + 2 * c;
        float2 v0 = *(const float2*)(bp);
        float2 v1 = *(const float2*)(bp + 8 * SXS);
        float2 v2 = *(const float2*)(bp + 8);
        float2 v3 = *(const float2*)(bp + 8 * SXS + 8);
        ah[t][0] = pack_bf2(v0.x, v0.y); al[t][0] = pack_bf2(v0.x - bf2_lo(ah[t][0]), v0.y - bf2_hi(ah[t][0]));
        ah[t][1] = pack_bf2(v1.x, v1.y); al[t][1] = pack_bf2(v1.x - bf2_lo(ah[t][1]), v1.y - bf2_hi(ah[t][1]));
        ah[t][2] = pack_bf2(v2.x, v2.y); al[t][2] = pack_bf2(v2.x - bf2_lo(ah[t][2]), v2.y - bf2_hi(ah[t][2]));
        ah[t][3] = pack_bf2(v3.x, v3.y); al[t][3] = pack_bf2(v3.x - bf2_lo(ah[t][3]), v3.y - bf2_hi(ah[t][3]));
    }
    #pragma unroll
    for (int nt = 0; nt < 8; ++nt) {
        const int f = nb * 64 + nt * 8 + q;
        uint4 B = *(const uint4*)(slot + f * 64 + slSel * 16);
        mma_bf16(acc[0][nt], ah[0][0], ah[0][1], ah[0][2], ah[0][3], B.x, B.y);
        mma_bf16(acc[0][nt], ah[0][0], ah[0][1], ah[0][2], ah[0][3], B.z, B.w);
        mma_bf16(acc[0][nt], al[0][0], al[0][1], al[0][2], al[0][3], B.x, B.y);
        mma_bf16(acc[1][nt], ah[1][0], ah[1][1], ah[1][2], ah[1][3], B.x, B.y);
        mma_bf16(acc[1][nt], ah[1][0], ah[1][1], ah[1][2], ah[1][3], B.z, B.w);
        mma_bf16(acc[1][nt], al[1][0], al[1][1], al[1][2], al[1][3], B.x, B.y);
    }
}

// ================= prep =================

__global__ void prep_w(const float* __restrict__ W1, const float* __restrict__ W2,
                       uint4* __restrict__ w1s, uint4* __restrict__ w2s)
{
    int i = blockIdx.x * 256 + threadIdx.x;
    const float* W; uint4* dst; int idx;
    if (i < 8192) { W = W1; dst = w1s; idx = i; }
    else          { W = W2; dst = w2s; idx = i - 8192; }
    const int s = idx >> 10;
    const int r = idx & 1023;
    const int f = r >> 2;
    const int slotIdx = r & 3;
    const int c = (slotIdx - (f >> 1)) & 3;
    const int k0 = s * 16 + 2 * c;
    float v0 = W[(size_t)(k0)     * 256 + f];
    float v1 = W[(size_t)(k0 + 1) * 256 + f];
    float v2 = W[(size_t)(k0 + 8) * 256 + f];
    float v3 = W[(size_t)(k0 + 9) * 256 + f];
    uint32_t h0 = pack_bf2(v0, v1);
    uint32_t h1 = pack_bf2(v2, v3);
    uint32_t l0 = pack_bf2(v0 - bf2_lo(h0), v1 - bf2_hi(h0));
    uint32_t l1 = pack_bf2(v2 - bf2_lo(h1), v3 - bf2_hi(h1));
    dst[s * 1024 + f * 4 + slotIdx] = make_uint4(h0, h1, l0, l1);
}

// ================= K2 (v7, unchanged) =================

__global__ __launch_bounds__(BDIM)
void k2_hmma(const float* __restrict__ f_ij, const float* __restrict__ r_ij,
             const float* __restrict__ nmask, const int* __restrict__ neigh,
             const uint4* __restrict__ w1s, const uint4* __restrict__ w2s,
             const float* __restrict__ b1, const float* __restrict__ b2,
             const float* __restrict__ XF, float* __restrict__ Y)
{
    extern __shared__ char smc[];
    float* sX   = (float*)smc;
    float* sM   = (float*)(smc + SMEM_M_OFF);
    int*   sRow = (int*)  (smc + SMEM_R_OFF);
    float* sRed = (float*)(smc + SMEM_RED_OFF);
    const uint32_t sbase = smem_u32(smc);
    const int tid = threadIdx.x, wid = tid >> 5, lane = tid & 31;
    const int q = lane >> 2, c = lane & 3;
    const int slSel = (c + (q >> 1)) & 3;
    const int mt = wid & 1, nb = wid >> 1;
    const int bid = blockIdx.x;

    stage_w(sbase, 0, w1s, 0, tid);
    CP_COMMIT();

    {
        const float4* f4 = (const float4*)(f_ij + (size_t)bid * 8192);
        #pragma unroll
        for (int u = 0; u < 8; ++u) {
            int i4 = tid + u * 256;
            int row = i4 >> 5, c4 = i4 & 31;
            *(float4*)(sX + row * SXS + c4 * 4) = f4[i4];
        }
    }
    if (tid < 64) {
        float r = r_ij[bid * 64 + tid];
        float m = nmask[bid * 64 + tid];
        sM[tid]   = (r <= CUTOFF) ? m : 0.0f;
        sRow[tid] = (bid >> 9) * 512 + neigh[bid * 64 + tid];
    }

    float acc[2][8][4];
    #pragma unroll
    for (int a = 0; a < 2; ++a)
        #pragma unroll
        for (int n = 0; n < 8; ++n)
            #pragma unroll
            for (int i = 0; i < 4; ++i) acc[a][n][i] = 0.0f;

    #pragma unroll 1
    for (int s = 0; s < 8; ++s) {
        CP_WAIT0();
        __syncthreads();
        if (s < 7) { stage_w(sbase, (s + 1) & 1, w1s, s + 1, tid); CP_COMMIT(); }
        gemm_kstep(acc, sX, s * 16, smc + SLOT_OFF + (s & 1) * BUF_BYTES, mt, nb, q, c, slSel);
    }
    __syncthreads();

    stage_w(sbase, 0, w2s, 0, tid);
    CP_COMMIT();

    #pragma unroll
    for (int nt = 0; nt < 8; ++nt) {
        const int col = nb * 64 + nt * 8 + 2 * c;
        float2 bv = *(const float2*)(b1 + col);
        #pragma unroll
        for (int t = 0; t < 2; ++t) {
            const int r0 = mt * 32 + t * 16 + q;
            *(float2*)(sX + r0 * SXS + col) =
                make_float2(sspf(acc[t][nt][0] + bv.x), sspf(acc[t][nt][1] + bv.y));
            *(float2*)(sX + (r0 + 8) * SXS + col) =
                make_float2(sspf(acc[t][nt][2] + bv.x), sspf(acc[t][nt][3] + bv.y));
        }
    }
    #pragma unroll
    for (int a = 0; a < 2; ++a)
        #pragma unroll
        for (int n = 0; n < 8; ++n)
            #pragma unroll
            for (int i = 0; i < 4; ++i) acc[a][n][i] = 0.0f;

    #pragma unroll 1
    for (int s = 0; s < 16; ++s) {
        CP_WAIT0();
        __syncthreads();
        if (s < 15) { stage_w(sbase, (s + 1) & 1, w2s, s + 1, tid); CP_COMMIT(); }
        gemm_kstep(acc, sX, s * 16, smc + SLOT_OFF + (s & 1) * BUF_BYTES, mt, nb, q, c, slSel);
    }
    __syncthreads();

    #pragma unroll
    for (int rr = 0; rr < 8; ++rr) {
        const int row = wid * 8 + rr;
        const float4* src = (const float4*)(XF + (size_t)sRow[row] * 256);
        *(float4*)(sX + row * SXS + lane * 4)        = src[lane];
        *(float4*)(sX + row * SXS + (lane + 32) * 4) = src[lane + 32];
    }
    __syncthreads();

    #pragma unroll
    for (int nt = 0; nt < 8; ++nt) {
        const int col = nb * 64 + nt * 8 + 2 * c;
        float2 bv = *(const float2*)(b2 + col);
        float pe = 0.0f, po = 0.0f;
        #pragma unroll
        for (int t = 0; t < 2; ++t) {
            #pragma unroll
            for (int p = 0; p < 2; ++p) {
                const int row = mt * 32 + t * 16 + q + 8 * p;
                const float m = sM[row];
                float2 x = *(const float2*)(sX + row * SXS + col);
                pe = fmaf(m * (acc[t][nt][2 * p]     + bv.x), x.x, pe);
                po = fmaf(m * (acc[t][nt][2 * p + 1] + bv.y), x.y, po);
            }
        }
        pe += __shfl_xor_sync(0xffffffffu, pe, 4);
        pe += __shfl_xor_sync(0xffffffffu, pe, 8);
        pe += __shfl_xor_sync(0xffffffffu, pe, 16);
        po += __shfl_xor_sync(0xffffffffu, po, 4);
        po += __shfl_xor_sync(0xffffffffu, po, 8);
        po += __shfl_xor_sync(0xffffffffu, po, 16);
        if (q == nt) {
            sRed[mt * 256 + col]     = pe;
            sRed[mt * 256 + col + 1] = po;
        }
    }
    __syncthreads();
    Y[(size_t)bid * 256 + tid] = sRed[tid] + sRed[256 + tid];
}

// ================= FFMA2 tile helper =================

template<int JROWS>
__device__ __forceinline__ void mma_tile8(const float* cur, const float* sA,
                                          int lda, int rowbase, int f0,
                                          unsigned long long (&acc)[JROWS][4])
{
    #pragma unroll
    for (int kq = 0; kq < 8; kq += 4) {
        float4 av[JROWS];
        #pragma unroll
        for (int j = 0; j < JROWS; ++j)
            av[j] = *(const float4*)&sA[(rowbase + j) * lda + kq];
        #pragma unroll
        for (int kk = 0; kk < 4; ++kk) {
            ulonglong2 bva = *(const ulonglong2*)&cur[(kq + kk) * 256 + f0];
            ulonglong2 bvb = *(const ulonglong2*)&cur[(kq + kk) * 256 + f0 + 4];
            #pragma unroll
            for (int j = 0; j < JROWS; ++j) {
                unsigned long long a2 = pack_dup(f4c(av[j], kk));
                fma2(acc[j][0], a2, bva.x);
                fma2(acc[j][1], a2, bva.y);
                fma2(acc[j][2], a2, bvb.x);
                fma2(acc[j][3], a2, bvb.y);
            }
        }
    }
}

// ================= K1: 16-row GEMM, C = A @ W (K=256, N=256) ================

__global__ __launch_bounds__(BDIM, 2)
void gemm16_kernel(const float* __restrict__ A, const float* __restrict__ W,
                   float* __restrict__ C)
{
    extern __shared__ float smem[];
    float* sA = smem;             // 16*256 = 4096
    float* sWa = smem + 4096;     // 2048
    float* sWb = smem + 6144;     // 2048
    const int tid = threadIdx.x, tn = tid >> 5;
    const int f0 = (tid & 31) * 8, r0 = tn * 2;
    {
        const float* src = A + (size_t)blockIdx.x * 4096;
        #pragma unroll
        for (int u = 0; u < 4; ++u)
            *(float4*)&sA[tid * 4 + u * 1024] = *(const float4*)&src[tid * 4 + u * 1024];
    }
    *(float4*)&sWa[tid * 8]     = *(const float4*)&W[tid * 8];
    *(float4*)&sWa[tid * 8 + 4] = *(const float4*)&W[tid * 8 + 4];
    __syncthreads();
    unsigned long long acc[2][4];
    #pragma unroll
    for (int j = 0; j < 2; ++j) { acc[j][0]=acc[j][1]=acc[j][2]=acc[j][3]=0ull; }
    #pragma unroll 1
    for (int k0 = 0; k0 < 256; k0 += 8) {
        const float* cur = ((k0 >> 3) & 1) ? sWb : sWa;
        float*       nxt = ((k0 >> 3) & 1) ? sWa : sWb;
        float4 p0, p1;
        const bool more = (k0 + 8) < 256;
        if (more) {
            p0 = *(const float4*)&W[(k0 + 8) * 256 + tid * 8];
            p1 = *(const float4*)&W[(k0 + 8) * 256 + tid * 8 + 4];
        }
        mma_tile8<2>(cur, sA + k0, 256, r0, f0, acc);
        if (more) { *(float4*)&nxt[tid * 8] = p0; *(float4*)&nxt[tid * 8 + 4] = p1; }
        __syncthreads();
    }
    #pragma unroll
    for (int j = 0; j < 2; ++j) {
        float w[8];
        #pragma unroll
        for (int i2 = 0; i2 < 4; ++i2) {
            float2 v = unpack2(acc[j][i2]); w[2*i2] = v.x; w[2*i2+1] = v.y;
        }
        const int row = blockIdx.x * 16 + r0 + j;
        *(float4*)&C[(size_t)row * 256 + f0]     = make_float4(w[0], w[1], w[2], w[3]);
        *(float4*)&C[(size_t)row * 256 + f0 + 4] = make_float4(w[4], w[5], w[6], w[7]);
    }
}

// ================= K3: 16-row fused tail =================

__global__ __launch_bounds__(BDIM, 2)
void tail16_kernel(const float* __restrict__ Yin, const float* __restrict__ Gin,
                   const float* __restrict__ W_f2out, const float* __restrict__ b_f2out,
                   const float* __restrict__ W_dense, const float* __restrict__ b_dense,
                   const float* __restrict__ W_ang, float* __restrict__ out)
{
    extern __shared__ float smem[];
    float* sY  = smem;             // 4096
    float* sT  = smem + 4096;      // 4096
    float* sG  = smem + 8192;      // 2048
    float* sWa = smem + 10240;     // 2048
    float* sWb = smem + 12288;     // 2048
    const int tid = threadIdx.x, tn = tid >> 5;
    const int f0 = (tid & 31) * 8, r0 = tn * 2;
    {
        const float* src = Yin + (size_t)blockIdx.x * 4096;
        #pragma unroll
        for (int u = 0; u < 4; ++u)
            *(float4*)&sY[tid * 4 + u * 1024] = *(const float4*)&src[tid * 4 + u * 1024];
        const float* srcg = Gin + (size_t)blockIdx.x * 2048;
        #pragma unroll
        for (int u = 0; u < 2; ++u)
            *(float4*)&sG[tid * 4 + u * 1024] = *(const float4*)&srcg[tid * 4 + u * 1024];
    }
    *(float4*)&sWa[tid * 8]     = *(const float4*)&W_f2out[tid * 8];
    *(float4*)&sWa[tid * 8 + 4] = *(const float4*)&W_f2out[tid * 8 + 4];
    __syncthreads();
    unsigned long long acc[2][4];
    #pragma unroll
    for (int j = 0; j < 2; ++j) { acc[j][0]=acc[j][1]=acc[j][2]=acc[j][3]=0ull; }
    // phase 1: T = Y @ W_f2out + b_f2out
    #pragma unroll 1
    for (int k0 = 0; k0 < 256; k0 += 8) {
        const float* cur = ((k0 >> 3) & 1) ? sWb : sWa;
        float*       nxt = ((k0 >> 3) & 1) ? sWa : sWb;
        float4 p0, p1;
        const bool more = (k0 + 8) < 256;
        if (more) {
            p0 = *(const float4*)&W_f2out[(k0 + 8) * 256 + tid * 8];
            p1 = *(const float4*)&W_f2out[(k0 + 8) * 256 + tid * 8 + 4];
        }
        mma_tile8<2>(cur, sY + k0, 256, r0, f0, acc);
        if (more) { *(float4*)&nxt[tid * 8] = p0; *(float4*)&nxt[tid * 8 + 4] = p1; }
        __syncthreads();
    }
    {
        float4 ba = *(const float4*)&b_f2out[f0];
        float4 bb4 = *(const float4*)&b_f2out[f0 + 4];
        float bb[8] = {ba.x, ba.y, ba.z, ba.w, bb4.x, bb4.y, bb4.z, bb4.w};
        #pragma unroll
        for (int j = 0; j < 2; ++j) {
            float w[8];
            #pragma unroll
            for (int i2 = 0; i2 < 4; ++i2) {
                float2 v = unpack2(acc[j][i2]);
                w[2*i2] = v.x + bb[2*i2]; w[2*i2+1] = v.y + bb[2*i2+1];
            }
            *(float4*)&sT[(r0 + j) * 256 + f0]     = make_float4(w[0], w[1], w[2], w[3]);
            *(float4*)&sT[(r0 + j) * 256 + f0 + 4] = make_float4(w[4], w[5], w[6], w[7]);
        }
    }
    __syncthreads();
    *(float4*)&sWa[tid * 8]     = *(const float4*)&W_dense[tid * 8];
    *(float4*)&sWa[tid * 8 + 4] = *(const float4*)&W_dense[tid * 8 + 4];
    #pragma unroll
    for (int j = 0; j < 2; ++j) { acc[j][0]=acc[j][1]=acc[j][2]=acc[j][3]=0ull; }
    __syncthreads();
    // phase 2a: U = T @ W_dense
    #pragma unroll 1
    for (int k0 = 0; k0 < 256; k0 += 8) {
        const float* cur = ((k0 >> 3) & 1) ? sWb : sWa;
        float*       nxt = ((k0 >> 3) & 1) ? sWa : sWb;
        float4 p0, p1;
        const bool more = (k0 + 8) < 256;
        if (more) {
            p0 = *(const float4*)&W_dense[(k0 + 8) * 256 + tid * 8];
            p1 = *(const float4*)&W_dense[(k0 + 8) * 256 + tid * 8 + 4];
        } else {
            p0 = *(const float4*)&W_ang[tid * 8];
            p1 = *(const float4*)&W_ang[tid * 8 + 4];
        }
        mma_tile8<2>(cur, sT + k0, 256, r0, f0, acc);
        *(float4*)&nxt[tid * 8] = p0; *(float4*)&nxt[tid * 8 + 4] = p1;
        __syncthreads();
    }
    // phase 2b: U += G @ W_ang (K=128)
    #pragma unroll 1
    for (int k0 = 0; k0 < 128; k0 += 8) {
        const float* cur = ((k0 >> 3) & 1) ? sWb : sWa;
        float*       nxt = ((k0 >> 3) & 1) ? sWa : sWb;
        float4 p0, p1;
        const bool more = (k0 + 8) < 128;
        if (more) {
            p0 = *(const float4*)&W_ang[(k0 + 8) * 256 + tid * 8];
            p1 = *(const float4*)&W_ang[(k0 + 8) * 256 + tid * 8 + 4];
        }
        mma_tile8<2>(cur, sG + k0, 128, r0, f0, acc);
        if (more) { *(float4*)&nxt[tid * 8] = p0; *(float4*)&nxt[tid * 8 + 4] = p1; }
        __syncthreads();
    }
    {
        float4 ba = *(const float4*)&b_dense[f0];
        float4 bb4 = *(const float4*)&b_dense[f0 + 4];
        float bb[8] = {ba.x, ba.y, ba.z, ba.w, bb4.x, bb4.y, bb4.z, bb4.w};
        #pragma unroll
        for (int j = 0; j < 2; ++j) {
            float w[8];
            #pragma unroll
            for (int i2 = 0; i2 < 4; ++i2) {
                float2 v = unpack2(acc[j][i2]);
                w[2*i2] = sspf(v.x + bb[2*i2]); w[2*i2+1] = sspf(v.y + bb[2*i2+1]);
            }
            const int row = blockIdx.x * 16 + r0 + j;
            *(float4*)&out[(size_t)row * 256 + f0]     = make_float4(w[0], w[1], w[2], w[3]);
            *(float4*)&out[(size_t)row * 256 + f0 + 4] = make_float4(w[4], w[5], w[6], w[7]);
        }
    }
}

// ---------------------------------------------------------------------------

extern "C" void kernel_launch(void* const* d_in, const int* in_sizes, int n_in,
                              void* d_out, int out_size)
{
    const float* x        = (const float*)d_in[0];
    const float* r_ij     = (const float*)d_in[1];
    const float* f_ij     = (const float*)d_in[2];
    const float* G_i      = (const float*)d_in[3];
    const float* nmask    = (const float*)d_in[4];
    const int*   neigh    = (const int*)  d_in[5];
    const float* W_in2f   = (const float*)d_in[6];
    const float* W1       = (const float*)d_in[7];
    const float* b1       = (const float*)d_in[8];
    const float* W2       = (const float*)d_in[9];
    const float* b2       = (const float*)d_in[10];
    const float* W_f2out  = (const float*)d_in[11];
    const float* b_f2out  = (const float*)d_in[12];
    const float* W_dense  = (const float*)d_in[13];
    const float* b_dense  = (const float*)d_in[14];
    const float* W_ang    = (const float*)d_in[15];
    float* out = (float*)d_out;

    float *pXF, *pY;
    uint4 *p1s, *p2s;
    cudaGetSymbolAddress((void**)&pXF, g_XF);
    cudaGetSymbolAddress((void**)&pY,  g_Y);
    cudaGetSymbolAddress((void**)&p1s, g_w1s);
    cudaGetSymbolAddress((void**)&p2s, g_w2s);

    const size_t smem1 = (4096 + 4096) * 4;    // 32,768
    const size_t smem2 = SMEM_K2_TOTAL;
    const size_t smem3 = (14336) * 4;          // 57,344

    cudaFuncSetAttribute(gemm16_kernel, cudaFuncAttributeMaxDynamicSharedMemorySize, (int)smem1);
    cudaFuncSetAttribute(k2_hmma,       cudaFuncAttributeMaxDynamicSharedMemorySize, (int)smem2);
    cudaFuncSetAttribute(tail16_kernel, cudaFuncAttributeMaxDynamicSharedMemorySize, (int)smem3);

    prep_w<<<96, 256>>>(W1, W2, p1s, p2s);
    gemm16_kernel<<<NATOMS / 16, BDIM, smem1>>>(x, W_in2f, pXF);
    k2_hmma<<<NATOMS, BDIM, smem2>>>(
        f_ij, r_ij, nmask, neigh, p1s, p2s, b1, b2, pXF, pY);
    tail16_kernel<<<NATOMS / 16, BDIM, smem3>>>(
        pY, G_i, W_f2out, b_f2out, W_dense, b_dense, W_ang, out);
}

// round 13
// speedup vs baseline: 1.2660x; 1.1937x over previous
#include <cuda_runtime.h>
#include <cuda_bf16.h>
#include <cstdint>

// ---------------------------------------------------------------------------
// SchNet interaction block, sm_103 — v13: all GEMMs on HMMA (mma.sync bf16).
//   prep:  all weights -> pre-swizzled bf16 hi/lo chunk images (prep_wg x6)
//   K1:    XF = x @ W_in2f                        (k1_hmma, M=32/CTA)
//   K2:    fused filter MLP + gather + aggregate  (k2_hmma, v7 frozen)
//   K3:    ssp((Y@Wf2o+b)@Wd + G@Wang + b)        (tail_hmma, M=32/CTA)
// GEMMs: D += Ahi*Bhi + Ahi*Blo + Alo*Bhi (bf16 splits, fp32 acc).
// ---------------------------------------------------------------------------

#define BDIM 256
#define NATOMS 4096
#define CUTOFF 5.0f

// K2 smem layout (bytes) — identical to v7
#define SXS        260
#define SLOT_OFF   66560
#define BUF_BYTES  16384
#define SMEM_M_OFF 99328
#define SMEM_R_OFF 99584
#define SMEM_RED_OFF 99840
#define SMEM_K2_TOTAL 101888

// K1 smem: sX 32 rows
#define K1_SLOT_OFF 33280
#define SMEM_K1_TOTAL 66048
// tail smem: sX 64 rows (rows 0..31 Y/T, rows 32..63 G)
#define T_SLOT_OFF 66560
#define SMEM_T_TOTAL 99328

__device__ float g_XF[NATOMS * 256];
__device__ float g_Y [NATOMS * 256];
__device__ __align__(16) uint4 g_w1s[8 * 1024];
__device__ __align__(16) uint4 g_w2s[16 * 1024];
__device__ __align__(16) uint4 g_wis[16 * 1024];   // W_in2f
__device__ __align__(16) uint4 g_wfs[16 * 1024];   // W_f2out
__device__ __align__(16) uint4 g_wdg[24 * 1024];   // W_dense (0..15) + W_ang (16..23)

// ================= helpers =================

__device__ __forceinline__ uint32_t smem_u32(const void* p) {
    uint32_t a;
    asm("{ .reg .u64 t; cvta.to.shared.u64 t, %1; cvt.u32.u64 %0, t; }" : "=r"(a) : "l"(p));
    return a;
}
__device__ __forceinline__ float sspf(float v) {
    float e = __expf(v);
    float r = __logf(fmaf(0.5f, e, 0.5f));
    return (v > 60.0f) ? (v - 0.69314718055994531f) : r;
}
__device__ __forceinline__ uint32_t pack_bf2(float v0, float v1) {
    uint32_t r;
    asm("cvt.rn.satfinite.bf16x2.f32 %0, %1, %2;" : "=r"(r) : "f"(v1), "f"(v0));
    return r;
}
__device__ __forceinline__ float bf2_lo(uint32_t p) { return __uint_as_float(p << 16); }
__device__ __forceinline__ float bf2_hi(uint32_t p) { return __uint_as_float(p & 0xffff0000u); }

__device__ __forceinline__ void mma_bf16(float* d, uint32_t a0, uint32_t a1, uint32_t a2, uint32_t a3,
                                         uint32_t b0, uint32_t b1) {
    asm volatile("mma.sync.aligned.m16n8k16.row.col.f32.bf16.bf16.f32 "
                 "{%0,%1,%2,%3}, {%4,%5,%6,%7}, {%8,%9}, {%0,%1,%2,%3};"
                 : "+f"(d[0]), "+f"(d[1]), "+f"(d[2]), "+f"(d[3])
                 : "r"(a0), "r"(a1), "r"(a2), "r"(a3), "r"(b0), "r"(b1));
}

__device__ __forceinline__ void cp16(uint32_t dst, const void* src) {
    asm volatile("cp.async.cg.shared.global [%0], [%1], 16;" :: "r"(dst), "l"(src) : "memory");
}
#define CP_COMMIT() asm volatile("cp.async.commit_group;" ::: "memory")
#define CP_WAIT0()  asm volatile("cp.async.wait_group 0;" ::: "memory")

// stage one pre-swizzled 16KB chunk image into smem at dstaddr (coalesced)
__device__ __forceinline__ void stage_at(uint32_t dstaddr, const uint4* ws, int s, int tid) {
    uint32_t d = dstaddr + (uint32_t)tid * 64;
    const char* g = (const char*)(ws + s * 1024) + tid * 64;
    cp16(d,      g);
    cp16(d + 16, g + 16);
    cp16(d + 32, g + 32);
    cp16(d + 48, g + 48);
}

// v7 full kstep: acc[2 mtiles][8 ntiles][4], M=64 (mt in {0,1}), N=256
__device__ __forceinline__ void gemm_kstep(float (&acc)[2][8][4], const float* sX, int k0,
                                           const char* slot, int mt, int nb, int q, int c,
                                           int slSel) {
    uint32_t ah[2][4], al[2][4];
    #pragma unroll
    for (int t = 0; t < 2; ++t) {
        const float* bp = sX + (mt * 32 + t * 16 + q) * SXS + k0 + 2 * c;
        float2 v0 = *(const float2*)(bp);
        float2 v1 = *(const float2*)(bp + 8 * SXS);
        float2 v2 = *(const float2*)(bp + 8);
        float2 v3 = *(const float2*)(bp + 8 * SXS + 8);
        ah[t][0] = pack_bf2(v0.x, v0.y); al[t][0] = pack_bf2(v0.x - bf2_lo(ah[t][0]), v0.y - bf2_hi(ah[t][0]));
        ah[t][1] = pack_bf2(v1.x, v1.y); al[t][1] = pack_bf2(v1.x - bf2_lo(ah[t][1]), v1.y - bf2_hi(ah[t][1]));
        ah[t][2] = pack_bf2(v2.x, v2.y); al[t][2] = pack_bf2(v2.x - bf2_lo(ah[t][2]), v2.y - bf2_hi(ah[t][2]));
        ah[t][3] = pack_bf2(v3.x, v3.y); al[t][3] = pack_bf2(v3.x - bf2_lo(ah[t][3]), v3.y - bf2_hi(ah[t][3]));
    }
    #pragma unroll
    for (int nt = 0; nt < 8; ++nt) {
        const int f = nb * 64 + nt * 8 + q;
        uint4 B = *(const uint4*)(slot + f * 64 + slSel * 16);
        mma_bf16(acc[0][nt], ah[0][0], ah[0][1], ah[0][2], ah[0][3], B.x, B.y);
        mma_bf16(acc[0][nt], ah[0][0], ah[0][1], ah[0][2], ah[0][3], B.z, B.w);
        mma_bf16(acc[0][nt], al[0][0], al[0][1], al[0][2], al[0][3], B.x, B.y);
        mma_bf16(acc[1][nt], ah[1][0], ah[1][1], ah[1][2], ah[1][3], B.x, B.y);
        mma_bf16(acc[1][nt], ah[1][0], ah[1][1], ah[1][2], ah[1][3], B.z, B.w);
        mma_bf16(acc[1][nt], al[1][0], al[1][1], al[1][2], al[1][3], B.x, B.y);
    }
}

// M=32 kstep: acc[2 t][4 nt][4]; each warp owns 32 N-cols (nb in 0..7).
// rowbase selects the A block (0 for Y/T/x, 32 for G).
__device__ __forceinline__ void gemm_kstep32(float (&acc)[2][4][4], const float* sX, int rowbase,
                                             int k0, const char* slot, int nb, int q, int c,
                                             int slSel) {
    uint32_t ah[2][4], al[2][4];
    #pragma unroll
    for (int t = 0; t < 2; ++t) {
        const float* bp = sX + (rowbase + t * 16 + q) * SXS + k0 + 2 * c;
        float2 v0 = *(const float2*)(bp);
        float2 v1 = *(const float2*)(bp + 8 * SXS);
        float2 v2 = *(const float2*)(bp + 8);
        float2 v3 = *(const float2*)(bp + 8 * SXS + 8);
        ah[t][0] = pack_bf2(v0.x, v0.y); al[t][0] = pack_bf2(v0.x - bf2_lo(ah[t][0]), v0.y - bf2_hi(ah[t][0]));
        ah[t][1] = pack_bf2(v1.x, v1.y); al[t][1] = pack_bf2(v1.x - bf2_lo(ah[t][1]), v1.y - bf2_hi(ah[t][1]));
        ah[t][2] = pack_bf2(v2.x, v2.y); al[t][2] = pack_bf2(v2.x - bf2_lo(ah[t][2]), v2.y - bf2_hi(ah[t][2]));
        ah[t][3] = pack_bf2(v3.x, v3.y); al[t][3] = pack_bf2(v3.x - bf2_lo(ah[t][3]), v3.y - bf2_hi(ah[t][3]));
    }
    #pragma unroll
    for (int nt = 0; nt < 4; ++nt) {
        const int f = nb * 32 + nt * 8 + q;
        uint4 B = *(const uint4*)(slot + f * 64 + slSel * 16);
        mma_bf16(acc[0][nt], ah[0][0], ah[0][1], ah[0][2], ah[0][3], B.x, B.y);
        mma_bf16(acc[0][nt], ah[0][0], ah[0][1], ah[0][2], ah[0][3], B.z, B.w);
        mma_bf16(acc[0][nt], al[0][0], al[0][1], al[0][2], al[0][3], B.x, B.y);
        mma_bf16(acc[1][nt], ah[1][0], ah[1][1], ah[1][2], ah[1][3], B.x, B.y);
        mma_bf16(acc[1][nt], ah[1][0], ah[1][1], ah[1][2], ah[1][3], B.z, B.w);
        mma_bf16(acc[1][nt], al[1][0], al[1][1], al[1][2], al[1][3], B.x, B.y);
    }
}

// ================= prep: generic pre-swizzled chunk images =================
// W: [nchunks*16, 256] row-major fp32.  Record (s, f, slot): slot=(c+(f>>1))&3
// holds k-pair c: {hi(k0+2c,+1), hi(k0+8+2c,+1), lo(...), lo(...)}, k0=16s.

__global__ void prep_wg(const float* __restrict__ W, uint4* __restrict__ dst, int nrec)
{
    int i = blockIdx.x * 256 + threadIdx.x;
    if (i >= nrec) return;
    const int s = i >> 10;
    const int r = i & 1023;
    const int f = r >> 2;
    const int slotIdx = r & 3;
    const int c = (slotIdx - (f >> 1)) & 3;
    const int k0 = s * 16 + 2 * c;
    float v0 = W[(size_t)(k0)     * 256 + f];
    float v1 = W[(size_t)(k0 + 1) * 256 + f];
    float v2 = W[(size_t)(k0 + 8) * 256 + f];
    float v3 = W[(size_t)(k0 + 9) * 256 + f];
    uint32_t h0 = pack_bf2(v0, v1);
    uint32_t h1 = pack_bf2(v2, v3);
    uint32_t l0 = pack_bf2(v0 - bf2_lo(h0), v1 - bf2_hi(h0));
    uint32_t l1 = pack_bf2(v2 - bf2_lo(h1), v3 - bf2_hi(h1));
    dst[s * 1024 + f * 4 + slotIdx] = make_uint4(h0, h1, l0, l1);
}

// ================= K2 (v7, unchanged) =================

__global__ __launch_bounds__(BDIM)
void k2_hmma(const float* __restrict__ f_ij, const float* __restrict__ r_ij,
             const float* __restrict__ nmask, const int* __restrict__ neigh,
             const uint4* __restrict__ w1s, const uint4* __restrict__ w2s,
             const float* __restrict__ b1, const float* __restrict__ b2,
             const float* __restrict__ XF, float* __restrict__ Y)
{
    extern __shared__ char smc[];
    float* sX   = (float*)smc;
    float* sM   = (float*)(smc + SMEM_M_OFF);
    int*   sRow = (int*)  (smc + SMEM_R_OFF);
    float* sRed = (float*)(smc + SMEM_RED_OFF);
    const uint32_t sbase = smem_u32(smc);
    const int tid = threadIdx.x, wid = tid >> 5, lane = tid & 31;
    const int q = lane >> 2, c = lane & 3;
    const int slSel = (c + (q >> 1)) & 3;
    const int mt = wid & 1, nb = wid >> 1;
    const int bid = blockIdx.x;

    stage_at(sbase + SLOT_OFF, w1s, 0, tid);
    CP_COMMIT();

    {
        const float4* f4 = (const float4*)(f_ij + (size_t)bid * 8192);
        #pragma unroll
        for (int u = 0; u < 8; ++u) {
            int i4 = tid + u * 256;
            int row = i4 >> 5, c4 = i4 & 31;
            *(float4*)(sX + row * SXS + c4 * 4) = f4[i4];
        }
    }
    if (tid < 64) {
        float r = r_ij[bid * 64 + tid];
        float m = nmask[bid * 64 + tid];
        sM[tid]   = (r <= CUTOFF) ? m : 0.0f;
        sRow[tid] = (bid >> 9) * 512 + neigh[bid * 64 + tid];
    }

    float acc[2][8][4];
    #pragma unroll
    for (int a = 0; a < 2; ++a)
        #pragma unroll
        for (int n = 0; n < 8; ++n)
            #pragma unroll
            for (int i = 0; i < 4; ++i) acc[a][n][i] = 0.0f;

    #pragma unroll 1
    for (int s = 0; s < 8; ++s) {
        CP_WAIT0();
        __syncthreads();
        if (s < 7) { stage_at(sbase + SLOT_OFF + ((s + 1) & 1) * BUF_BYTES, w1s, s + 1, tid); CP_COMMIT(); }
        gemm_kstep(acc, sX, s * 16, smc + SLOT_OFF + (s & 1) * BUF_BYTES, mt, nb, q, c, slSel);
    }
    __syncthreads();

    stage_at(sbase + SLOT_OFF, w2s, 0, tid);
    CP_COMMIT();

    #pragma unroll
    for (int nt = 0; nt < 8; ++nt) {
        const int col = nb * 64 + nt * 8 + 2 * c;
        float2 bv = *(const float2*)(b1 + col);
        #pragma unroll
        for (int t = 0; t < 2; ++t) {
            const int r0 = mt * 32 + t * 16 + q;
            *(float2*)(sX + r0 * SXS + col) =
                make_float2(sspf(acc[t][nt][0] + bv.x), sspf(acc[t][nt][1] + bv.y));
            *(float2*)(sX + (r0 + 8) * SXS + col) =
                make_float2(sspf(acc[t][nt][2] + bv.x), sspf(acc[t][nt][3] + bv.y));
        }
    }
    #pragma unroll
    for (int a = 0; a < 2; ++a)
        #pragma unroll
        for (int n = 0; n < 8; ++n)
            #pragma unroll
            for (int i = 0; i < 4; ++i) acc[a][n][i] = 0.0f;

    #pragma unroll 1
    for (int s = 0; s < 16; ++s) {
        CP_WAIT0();
        __syncthreads();
        if (s < 15) { stage_at(sbase + SLOT_OFF + ((s + 1) & 1) * BUF_BYTES, w2s, s + 1, tid); CP_COMMIT(); }
        gemm_kstep(acc, sX, s * 16, smc + SLOT_OFF + (s & 1) * BUF_BYTES, mt, nb, q, c, slSel);
    }
    __syncthreads();

    #pragma unroll
    for (int rr = 0; rr < 8; ++rr) {
        const int row = wid * 8 + rr;
        const float4* src = (const float4*)(XF + (size_t)sRow[row] * 256);
        *(float4*)(sX + row * SXS + lane * 4)        = src[lane];
        *(float4*)(sX + row * SXS + (lane + 32) * 4) = src[lane + 32];
    }
    __syncthreads();

    #pragma unroll
    for (int nt = 0; nt < 8; ++nt) {
        const int col = nb * 64 + nt * 8 + 2 * c;
        float2 bv = *(const float2*)(b2 + col);
        float pe = 0.0f, po = 0.0f;
        #pragma unroll
        for (int t = 0; t < 2; ++t) {
            #pragma unroll
            for (int p = 0; p < 2; ++p) {
                const int row = mt * 32 + t * 16 + q + 8 * p;
                const float m = sM[row];
                float2 x = *(const float2*)(sX + row * SXS + col);
                pe = fmaf(m * (acc[t][nt][2 * p]     + bv.x), x.x, pe);
                po = fmaf(m * (acc[t][nt][2 * p + 1] + bv.y), x.y, po);
            }
        }
        pe += __shfl_xor_sync(0xffffffffu, pe, 4);
        pe += __shfl_xor_sync(0xffffffffu, pe, 8);
        pe += __shfl_xor_sync(0xffffffffu, pe, 16);
        po += __shfl_xor_sync(0xffffffffu, po, 4);
        po += __shfl_xor_sync(0xffffffffu, po, 8);
        po += __shfl_xor_sync(0xffffffffu, po, 16);
        if (q == nt) {
            sRed[mt * 256 + col]     = pe;
            sRed[mt * 256 + col + 1] = po;
        }
    }
    __syncthreads();
    Y[(size_t)bid * 256 + tid] = sRed[tid] + sRed[256 + tid];
}

// ================= K1: XF = x @ W_in2f (HMMA, M=32/CTA) =================

__global__ __launch_bounds__(BDIM)
void k1_hmma(const float* __restrict__ x, const uint4* __restrict__ wis,
             float* __restrict__ XF)
{
    extern __shared__ char smc[];
    float* sX = (float*)smc;
    const uint32_t sbase = smem_u32(smc);
    const int tid = threadIdx.x, wid = tid >> 5, lane = tid & 31;
    const int q = lane >> 2, c = lane & 3;
    const int slSel = (c + (q >> 1)) & 3;
    const int nb = wid;
    const int bid = blockIdx.x;

    stage_at(sbase + K1_SLOT_OFF, wis, 0, tid);
    CP_COMMIT();

    {   // x rows [bid*32 .. +31], 256 cols
        const float4* f4 = (const float4*)(x + (size_t)bid * 8192);
        #pragma unroll
        for (int u = 0; u < 8; ++u) {
            int i4 = tid + u * 256;
            int row = i4 >> 6, c4 = i4 & 63;
            *(float4*)(sX + row * SXS + c4 * 4) = f4[i4];
        }
    }

    float acc[2][4][4];
    #pragma unroll
    for (int a = 0; a < 2; ++a)
        #pragma unroll
        for (int n = 0; n < 4; ++n)
            #pragma unroll
            for (int i = 0; i < 4; ++i) acc[a][n][i] = 0.0f;

    #pragma unroll 1
    for (int s = 0; s < 16; ++s) {
        CP_WAIT0();
        __syncthreads();
        if (s < 15) { stage_at(sbase + K1_SLOT_OFF + ((s + 1) & 1) * BUF_BYTES, wis, s + 1, tid); CP_COMMIT(); }
        gemm_kstep32(acc, sX, 0, s * 16, smc + K1_SLOT_OFF + (s & 1) * BUF_BYTES, nb, q, c, slSel);
    }
    __syncthreads();   // sX (x) dead; reuse as staging

    #pragma unroll
    for (int nt = 0; nt < 4; ++nt) {
        const int col = nb * 32 + nt * 8 + 2 * c;
        #pragma unroll
        for (int t = 0; t < 2; ++t) {
            const int r0 = t * 16 + q;
            *(float2*)(sX + r0 * SXS + col)       = make_float2(acc[t][nt][0], acc[t][nt][1]);
            *(float2*)(sX + (r0 + 8) * SXS + col) = make_float2(acc[t][nt][2], acc[t][nt][3]);
        }
    }
    __syncthreads();
    {   // coalesced store 32x256
        float4* dst = (float4*)(XF + (size_t)bid * 8192);
        #pragma unroll
        for (int u = 0; u < 8; ++u) {
            int i4 = tid + u * 256;
            int row = i4 >> 6, c4 = i4 & 63;
            dst[i4] = *(const float4*)(sX + row * SXS + c4 * 4);
        }
    }
}

// ================= K3: tail (HMMA, M=32/CTA) =================
// out = ssp((Y@Wf2o + bf) @ Wd + G @ Wang + bd)
// sX rows 0..31: Y then T then output staging; rows 32..63: G (128 cols).

__global__ __launch_bounds__(BDIM)
void tail_hmma(const float* __restrict__ Yin, const float* __restrict__ Gin,
               const uint4* __restrict__ wfs, const float* __restrict__ bf,
               const uint4* __restrict__ wdg, const float* __restrict__ bd,
               float* __restrict__ out)
{
    extern __shared__ char smc[];
    float* sX = (float*)smc;
    const uint32_t sbase = smem_u32(smc);
    const int tid = threadIdx.x, wid = tid >> 5, lane = tid & 31;
    const int q = lane >> 2, c = lane & 3;
    const int slSel = (c + (q >> 1)) & 3;
    const int nb = wid;
    const int bid = blockIdx.x;

    stage_at(sbase + T_SLOT_OFF, wfs, 0, tid);
    CP_COMMIT();

    {   // Y rows [bid*32..+31] -> sX rows 0..31
        const float4* f4 = (const float4*)(Yin + (size_t)bid * 8192);
        #pragma unroll
        for (int u = 0; u < 8; ++u) {
            int i4 = tid + u * 256;
            int row = i4 >> 6, c4 = i4 & 63;
            *(float4*)(sX + row * SXS + c4 * 4) = f4[i4];
        }
        // G rows -> sX rows 32..63 (cols 0..127)
        const float4* g4 = (const float4*)(Gin + (size_t)bid * 4096);
        #pragma unroll
        for (int u = 0; u < 4; ++u) {
            int i4 = tid + u * 256;
            int row = i4 >> 5, c4 = i4 & 31;
            *(float4*)(sX + (32 + row) * SXS + c4 * 4) = g4[i4];
        }
    }

    float acc[2][4][4];
    #pragma unroll
    for (int a = 0; a < 2; ++a)
        #pragma unroll
        for (int n = 0; n < 4; ++n)
            #pragma unroll
            for (int i = 0; i < 4; ++i) acc[a][n][i] = 0.0f;

    // phase A: T = Y @ W_f2out + bf
    #pragma unroll 1
    for (int s = 0; s < 16; ++s) {
        CP_WAIT0();
        __syncthreads();
        if (s < 15) { stage_at(sbase + T_SLOT_OFF + ((s + 1) & 1) * BUF_BYTES, wfs, s + 1, tid); CP_COMMIT(); }
        gemm_kstep32(acc, sX, 0, s * 16, smc + T_SLOT_OFF + (s & 1) * BUF_BYTES, nb, q, c, slSel);
    }
    __syncthreads();   // Y dead

    stage_at(sbase + T_SLOT_OFF, wdg, 0, tid);
    CP_COMMIT();

    // T -> sX rows 0..31
    #pragma unroll
    for (int nt = 0; nt < 4; ++nt) {
        const int col = nb * 32 + nt * 8 + 2 * c;
        float2 bv = *(const float2*)(bf + col);
        #pragma unroll
        for (int t = 0; t < 2; ++t) {
            const int r0 = t * 16 + q;
            *(float2*)(sX + r0 * SXS + col) =
                make_float2(acc[t][nt][0] + bv.x, acc[t][nt][1] + bv.y);
            *(float2*)(sX + (r0 + 8) * SXS + col) =
                make_float2(acc[t][nt][2] + bv.x, acc[t][nt][3] + bv.y);
        }
    }
    #pragma unroll
    for (int a = 0; a < 2; ++a)
        #pragma unroll
        for (int n = 0; n < 4; ++n)
            #pragma unroll
            for (int i = 0; i < 4; ++i) acc[a][n][i] = 0.0f;

    // phase B: U = T @ W_dense (ksteps 0..15) + G @ W_ang (ksteps 16..23)
    #pragma unroll 1
    for (int s = 0; s < 24; ++s) {
        CP_WAIT0();
        __syncthreads();
        if (s < 23) { stage_at(sbase + T_SLOT_OFF + ((s + 1) & 1) * BUF_BYTES, wdg, s + 1, tid); CP_COMMIT(); }
        const int rowbase = (s < 16) ? 0 : 32;
        const int k0 = (s < 16) ? s * 16 : (s - 16) * 16;
        gemm_kstep32(acc, sX, rowbase, k0, smc + T_SLOT_OFF + (s & 1) * BUF_BYTES, nb, q, c, slSel);
    }
    __syncthreads();   // T/G dead

    // out = ssp(U + bd), staged via sX rows 0..31 then coalesced store
    #pragma unroll
    for (int nt = 0; nt < 4; ++nt) {
        const int col = nb * 32 + nt * 8 + 2 * c;
        float2 bv = *(const float2*)(bd + col);
        #pragma unroll
        for (int t = 0; t < 2; ++t) {
            const int r0 = t * 16 + q;
            *(float2*)(sX + r0 * SXS + col) =
                make_float2(sspf(acc[t][nt][0] + bv.x), sspf(acc[t][nt][1] + bv.y));
            *(float2*)(sX + (r0 + 8) * SXS + col) =
                make_float2(sspf(acc[t][nt][2] + bv.x), sspf(acc[t][nt][3] + bv.y));
        }
    }
    __syncthreads();
    {
        float4* dst = (float4*)(out + (size_t)bid * 8192);
        #pragma unroll
        for (int u = 0; u < 8; ++u) {
            int i4 = tid + u * 256;
            int row = i4 >> 6, c4 = i4 & 63;
            dst[i4] = *(const float4*)(sX + row * SXS + c4 * 4);
        }
    }
}

// ---------------------------------------------------------------------------

extern "C" void kernel_launch(void* const* d_in, const int* in_sizes, int n_in,
                              void* d_out, int out_size)
{
    const float* x        = (const float*)d_in[0];
    const float* r_ij     = (const float*)d_in[1];
    const float* f_ij     = (const float*)d_in[2];
    const float* G_i      = (const float*)d_in[3];
    const float* nmask    = (const float*)d_in[4];
    const int*   neigh    = (const int*)  d_in[5];
    const float* W_in2f   = (const float*)d_in[6];
    const float* W1       = (const float*)d_in[7];
    const float* b1       = (const float*)d_in[8];
    const float* W2       = (const float*)d_in[9];
    const float* b2       = (const float*)d_in[10];
    const float* W_f2out  = (const float*)d_in[11];
    const float* b_f2out  = (const float*)d_in[12];
    const float* W_dense  = (const float*)d_in[13];
    const float* b_dense  = (const float*)d_in[14];
    const float* W_ang    = (const float*)d_in[15];
    float* out = (float*)d_out;

    float *pXF, *pY;
    uint4 *p1s, *p2s, *pis, *pfs, *pdg;
    cudaGetSymbolAddress((void**)&pXF, g_XF);
    cudaGetSymbolAddress((void**)&pY,  g_Y);
    cudaGetSymbolAddress((void**)&p1s, g_w1s);
    cudaGetSymbolAddress((void**)&p2s, g_w2s);
    cudaGetSymbolAddress((void**)&pis, g_wis);
    cudaGetSymbolAddress((void**)&pfs, g_wfs);
    cudaGetSymbolAddress((void**)&pdg, g_wdg);

    cudaFuncSetAttribute(k1_hmma,   cudaFuncAttributeMaxDynamicSharedMemorySize, SMEM_K1_TOTAL);
    cudaFuncSetAttribute(k2_hmma,   cudaFuncAttributeMaxDynamicSharedMemorySize, SMEM_K2_TOTAL);
    cudaFuncSetAttribute(tail_hmma, cudaFuncAttributeMaxDynamicSharedMemorySize, SMEM_T_TOTAL);

    prep_wg<<<32, 256>>>(W1,      p1s, 8 * 1024);
    prep_wg<<<64, 256>>>(W2,      p2s, 16 * 1024);
    prep_wg<<<64, 256>>>(W_in2f,  pis, 16 * 1024);
    prep_wg<<<64, 256>>>(W_f2out, pfs, 16 * 1024);
    prep_wg<<<64, 256>>>(W_dense, pdg, 16 * 1024);
    prep_wg<<<32, 256>>>(W_ang,   pdg + 16 * 1024, 8 * 1024);

    k1_hmma<<<NATOMS / 32, BDIM, SMEM_K1_TOTAL>>>(x, pis, pXF);
    k2_hmma<<<NATOMS, BDIM, SMEM_K2_TOTAL>>>(
        f_ij, r_ij, nmask, neigh, p1s, p2s, b1, b2, pXF, pY);
    tail_hmma<<<NATOMS / 32, BDIM, SMEM_T_TOTAL>>>(
        pY, G_i, pfs, b_f2out, pdg, b_dense, out);
}

// round 14
// speedup vs baseline: 1.3167x; 1.0400x over previous
#include <cuda_runtime.h>
#include <cuda_bf16.h>
#include <cstdint>

// ---------------------------------------------------------------------------
// SchNet interaction block, sm_103 — v14: v13 + merged prep + cp.async F/XF.
//   prep:  ALL weights -> pre-swizzled bf16 hi/lo chunk images (prep_all, 1 launch)
//   K1:    XF = x @ W_in2f                        (k1_hmma, M=32/CTA)
//   K2:    fused filter MLP + gather + aggregate  (k2_hmma, v7 core)
//   K3:    ssp((Y@Wf2o+b)@Wd + G@Wang + b)        (tail_hmma, M=32/CTA)
// GEMMs: D += Ahi*Bhi + Ahi*Blo + Alo*Bhi (bf16 splits, fp32 acc).
// ---------------------------------------------------------------------------

#define BDIM 256
#define NATOMS 4096
#define CUTOFF 5.0f

// K2 smem layout (bytes)
#define SXS        260
#define SLOT_OFF   66560
#define BUF_BYTES  16384
#define SMEM_M_OFF 99328
#define SMEM_R_OFF 99584
#define SMEM_RED_OFF 99840
#define SMEM_K2_TOTAL 101888

// K1 smem
#define K1_SLOT_OFF 33280
#define SMEM_K1_TOTAL 66048
// tail smem
#define T_SLOT_OFF 66560
#define SMEM_T_TOTAL 99328

__device__ float g_XF[NATOMS * 256];
__device__ float g_Y [NATOMS * 256];
__device__ __align__(16) uint4 g_w1s[8 * 1024];
__device__ __align__(16) uint4 g_w2s[16 * 1024];
__device__ __align__(16) uint4 g_wis[16 * 1024];   // W_in2f
__device__ __align__(16) uint4 g_wfs[16 * 1024];   // W_f2out
__device__ __align__(16) uint4 g_wdg[24 * 1024];   // W_dense (0..15) + W_ang (16..23)

// ================= helpers =================

__device__ __forceinline__ uint32_t smem_u32(const void* p) {
    uint32_t a;
    asm("{ .reg .u64 t; cvta.to.shared.u64 t, %1; cvt.u32.u64 %0, t; }" : "=r"(a) : "l"(p));
    return a;
}
__device__ __forceinline__ float sspf(float v) {
    float e = __expf(v);
    float r = __logf(fmaf(0.5f, e, 0.5f));
    return (v > 60.0f) ? (v - 0.69314718055994531f) : r;
}
__device__ __forceinline__ uint32_t pack_bf2(float v0, float v1) {
    uint32_t r;
    asm("cvt.rn.satfinite.bf16x2.f32 %0, %1, %2;" : "=r"(r) : "f"(v1), "f"(v0));
    return r;
}
__device__ __forceinline__ float bf2_lo(uint32_t p) { return __uint_as_float(p << 16); }
__device__ __forceinline__ float bf2_hi(uint32_t p) { return __uint_as_float(p & 0xffff0000u); }

__device__ __forceinline__ void mma_bf16(float* d, uint32_t a0, uint32_t a1, uint32_t a2, uint32_t a3,
                                         uint32_t b0, uint32_t b1) {
    asm volatile("mma.sync.aligned.m16n8k16.row.col.f32.bf16.bf16.f32 "
                 "{%0,%1,%2,%3}, {%4,%5,%6,%7}, {%8,%9}, {%0,%1,%2,%3};"
                 : "+f"(d[0]), "+f"(d[1]), "+f"(d[2]), "+f"(d[3])
                 : "r"(a0), "r"(a1), "r"(a2), "r"(a3), "r"(b0), "r"(b1));
}

__device__ __forceinline__ void cp16(uint32_t dst, const void* src) {
    asm volatile("cp.async.cg.shared.global [%0], [%1], 16;" :: "r"(dst), "l"(src) : "memory");
}
#define CP_COMMIT() asm volatile("cp.async.commit_group;" ::: "memory")
#define CP_WAIT0()  asm volatile("cp.async.wait_group 0;" ::: "memory")

__device__ __forceinline__ void stage_at(uint32_t dstaddr, const uint4* ws, int s, int tid) {
    uint32_t d = dstaddr + (uint32_t)tid * 64;
    const char* g = (const char*)(ws + s * 1024) + tid * 64;
    cp16(d,      g);
    cp16(d + 16, g + 16);
    cp16(d + 32, g + 32);
    cp16(d + 48, g + 48);
}

// v7 full kstep: acc[2 mtiles][8 ntiles][4], M=64, N=256
__device__ __forceinline__ void gemm_kstep(float (&acc)[2][8][4], const float* sX, int k0,
                                           const char* slot, int mt, int nb, int q, int c,
                                           int slSel) {
    uint32_t ah[2][4], al[2][4];
    #pragma unroll
    for (int t = 0; t < 2; ++t) {
        const float* bp = sX + (mt * 32 + t * 16 + q) * SXS + k0 + 2 * c;
        float2 v0 = *(const float2*)(bp);
        float2 v1 = *(const float2*)(bp + 8 * SXS);
        float2 v2 = *(const float2*)(bp + 8);
        float2 v3 = *(const float2*)(bp + 8 * SXS + 8);
        ah[t][0] = pack_bf2(v0.x, v0.y); al[t][0] = pack_bf2(v0.x - bf2_lo(ah[t][0]), v0.y - bf2_hi(ah[t][0]));
        ah[t][1] = pack_bf2(v1.x, v1.y); al[t][1] = pack_bf2(v1.x - bf2_lo(ah[t][1]), v1.y - bf2_hi(ah[t][1]));
        ah[t][2] = pack_bf2(v2.x, v2.y); al[t][2] = pack_bf2(v2.x - bf2_lo(ah[t][2]), v2.y - bf2_hi(ah[t][2]));
        ah[t][3] = pack_bf2(v3.x, v3.y); al[t][3] = pack_bf2(v3.x - bf2_lo(ah[t][3]), v3.y - bf2_hi(ah[t][3]));
    }
    #pragma unroll
    for (int nt = 0; nt < 8; ++nt) {
        const int f = nb * 64 + nt * 8 + q;
        uint4 B = *(const uint4*)(slot + f * 64 + slSel * 16);
        mma_bf16(acc[0][nt], ah[0][0], ah[0][1], ah[0][2], ah[0][3], B.x, B.y);
        mma_bf16(acc[0][nt], ah[0][0], ah[0][1], ah[0][2], ah[0][3], B.z, B.w);
        mma_bf16(acc[0][nt], al[0][0], al[0][1], al[0][2], al[0][3], B.x, B.y);
        mma_bf16(acc[1][nt], ah[1][0], ah[1][1], ah[1][2], ah[1][3], B.x, B.y);
        mma_bf16(acc[1][nt], ah[1][0], ah[1][1], ah[1][2], ah[1][3], B.z, B.w);
        mma_bf16(acc[1][nt], al[1][0], al[1][1], al[1][2], al[1][3], B.x, B.y);
    }
}

// M=32 kstep: acc[2 t][4 nt][4]; warp owns 32 N-cols (nb in 0..7)
__device__ __forceinline__ void gemm_kstep32(float (&acc)[2][4][4], const float* sX, int rowbase,
                                             int k0, const char* slot, int nb, int q, int c,
                                             int slSel) {
    uint32_t ah[2][4], al[2][4];
    #pragma unroll
    for (int t = 0; t < 2; ++t) {
        const float* bp = sX + (rowbase + t * 16 + q) * SXS + k0 + 2 * c;
        float2 v0 = *(const float2*)(bp);
        float2 v1 = *(const float2*)(bp + 8 * SXS);
        float2 v2 = *(const float2*)(bp + 8);
        float2 v3 = *(const float2*)(bp + 8 * SXS + 8);
        ah[t][0] = pack_bf2(v0.x, v0.y); al[t][0] = pack_bf2(v0.x - bf2_lo(ah[t][0]), v0.y - bf2_hi(ah[t][0]));
        ah[t][1] = pack_bf2(v1.x, v1.y); al[t][1] = pack_bf2(v1.x - bf2_lo(ah[t][1]), v1.y - bf2_hi(ah[t][1]));
        ah[t][2] = pack_bf2(v2.x, v2.y); al[t][2] = pack_bf2(v2.x - bf2_lo(ah[t][2]), v2.y - bf2_hi(ah[t][2]));
        ah[t][3] = pack_bf2(v3.x, v3.y); al[t][3] = pack_bf2(v3.x - bf2_lo(ah[t][3]), v3.y - bf2_hi(ah[t][3]));
    }
    #pragma unroll
    for (int nt = 0; nt < 4; ++nt) {
        const int f = nb * 32 + nt * 8 + q;
        uint4 B = *(const uint4*)(slot + f * 64 + slSel * 16);
        mma_bf16(acc[0][nt], ah[0][0], ah[0][1], ah[0][2], ah[0][3], B.x, B.y);
        mma_bf16(acc[0][nt], ah[0][0], ah[0][1], ah[0][2], ah[0][3], B.z, B.w);
        mma_bf16(acc[0][nt], al[0][0], al[0][1], al[0][2], al[0][3], B.x, B.y);
        mma_bf16(acc[1][nt], ah[1][0], ah[1][1], ah[1][2], ah[1][3], B.x, B.y);
        mma_bf16(acc[1][nt], ah[1][0], ah[1][1], ah[1][2], ah[1][3], B.z, B.w);
        mma_bf16(acc[1][nt], al[1][0], al[1][1], al[1][2], al[1][3], B.x, B.y);
    }
}

// ================= prep: ALL weights in one launch =================

__global__ void prep_all(const float* __restrict__ W1, const float* __restrict__ W2,
                         const float* __restrict__ Wi, const float* __restrict__ Wf,
                         const float* __restrict__ Wd, const float* __restrict__ Wa,
                         uint4* __restrict__ p1s, uint4* __restrict__ p2s,
                         uint4* __restrict__ pis, uint4* __restrict__ pfs,
                         uint4* __restrict__ pdg)
{
    int i = blockIdx.x * 256 + threadIdx.x;   // 81920 total
    const float* W; uint4* dst; int idx;
    if      (i < 8192)  { W = W1; dst = p1s;             idx = i; }
    else if (i < 24576) { W = W2; dst = p2s;             idx = i - 8192; }
    else if (i < 40960) { W = Wi; dst = pis;             idx = i - 24576; }
    else if (i < 57344) { W = Wf; dst = pfs;             idx = i - 40960; }
    else if (i < 73728) { W = Wd; dst = pdg;             idx = i - 57344; }
    else if (i < 81920) { W = Wa; dst = pdg + 16 * 1024; idx = i - 73728; }
    else return;
    const int s = idx >> 10;
    const int r = idx & 1023;
    const int f = r >> 2;
    const int slotIdx = r & 3;
    const int c = (slotIdx - (f >> 1)) & 3;
    const int k0 = s * 16 + 2 * c;
    float v0 = W[(size_t)(k0)     * 256 + f];
    float v1 = W[(size_t)(k0 + 1) * 256 + f];
    float v2 = W[(size_t)(k0 + 8) * 256 + f];
    float v3 = W[(size_t)(k0 + 9) * 256 + f];
    uint32_t h0 = pack_bf2(v0, v1);
    uint32_t h1 = pack_bf2(v2, v3);
    uint32_t l0 = pack_bf2(v0 - bf2_lo(h0), v1 - bf2_hi(h0));
    uint32_t l1 = pack_bf2(v2 - bf2_lo(h1), v3 - bf2_hi(h1));
    dst[s * 1024 + f * 4 + slotIdx] = make_uint4(h0, h1, l0, l1);
}

// ================= K2 (v7 core + cp.async F/XF) =================

__global__ __launch_bounds__(BDIM)
void k2_hmma(const float* __restrict__ f_ij, const float* __restrict__ r_ij,
             const float* __restrict__ nmask, const int* __restrict__ neigh,
             const uint4* __restrict__ w1s, const uint4* __restrict__ w2s,
             const float* __restrict__ b1, const float* __restrict__ b2,
             const float* __restrict__ XF, float* __restrict__ Y)
{
    extern __shared__ char smc[];
    float* sX   = (float*)smc;
    float* sM   = (float*)(smc + SMEM_M_OFF);
    int*   sRow = (int*)  (smc + SMEM_R_OFF);
    float* sRed = (float*)(smc + SMEM_RED_OFF);
    const uint32_t sbase = smem_u32(smc);
    const int tid = threadIdx.x, wid = tid >> 5, lane = tid & 31;
    const int q = lane >> 2, c = lane & 3;
    const int slSel = (c + (q >> 1)) & 3;
    const int mt = wid & 1, nb = wid >> 1;
    const int bid = blockIdx.x;

    // issue W1 chunk0 + F tile together (one cp.async group)
    stage_at(sbase + SLOT_OFF, w1s, 0, tid);
    {
        const char* fg = (const char*)(f_ij + (size_t)bid * 8192);
        #pragma unroll
        for (int u = 0; u < 8; ++u) {
            int unit = tid + u * 256;           // 0..2047 16B units
            int row = unit >> 5, c16 = unit & 31;
            cp16(sbase + (uint32_t)(row * 1040 + c16 * 16), fg + unit * 16);
        }
    }
    CP_COMMIT();

    if (tid < 64) {
        float r = r_ij[bid * 64 + tid];
        float m = nmask[bid * 64 + tid];
        sM[tid]   = (r <= CUTOFF) ? m : 0.0f;
        sRow[tid] = (bid >> 9) * 512 + neigh[bid * 64 + tid];
    }

    float acc[2][8][4];
    #pragma unroll
    for (int a = 0; a < 2; ++a)
        #pragma unroll
        for (int n = 0; n < 8; ++n)
            #pragma unroll
            for (int i = 0; i < 4; ++i) acc[a][n][i] = 0.0f;

    // ---- GEMM1: P = F @ W1 (8 ksteps) ----
    #pragma unroll 1
    for (int s = 0; s < 8; ++s) {
        CP_WAIT0();
        __syncthreads();
        if (s < 7) { stage_at(sbase + SLOT_OFF + ((s + 1) & 1) * BUF_BYTES, w1s, s + 1, tid); CP_COMMIT(); }
        gemm_kstep(acc, sX, s * 16, smc + SLOT_OFF + (s & 1) * BUF_BYTES, mt, nb, q, c, slSel);
    }
    __syncthreads();

    stage_at(sbase + SLOT_OFF, w2s, 0, tid);
    CP_COMMIT();

    // ---- H = ssp(P + b1) -> sX ----
    #pragma unroll
    for (int nt = 0; nt < 8; ++nt) {
        const int col = nb * 64 + nt * 8 + 2 * c;
        float2 bv = *(const float2*)(b1 + col);
        #pragma unroll
        for (int t = 0; t < 2; ++t) {
            const int r0 = mt * 32 + t * 16 + q;
            *(float2*)(sX + r0 * SXS + col) =
                make_float2(sspf(acc[t][nt][0] + bv.x), sspf(acc[t][nt][1] + bv.y));
            *(float2*)(sX + (r0 + 8) * SXS + col) =
                make_float2(sspf(acc[t][nt][2] + bv.x), sspf(acc[t][nt][3] + bv.y));
        }
    }
    #pragma unroll
    for (int a = 0; a < 2; ++a)
        #pragma unroll
        for (int n = 0; n < 8; ++n)
            #pragma unroll
            for (int i = 0; i < 4; ++i) acc[a][n][i] = 0.0f;

    // ---- GEMM2: Wf = H @ W2 (16 ksteps) ----
    #pragma unroll 1
    for (int s = 0; s < 16; ++s) {
        CP_WAIT0();
        __syncthreads();
        if (s < 15) { stage_at(sbase + SLOT_OFF + ((s + 1) & 1) * BUF_BYTES, w2s, s + 1, tid); CP_COMMIT(); }
        gemm_kstep(acc, sX, s * 16, smc + SLOT_OFF + (s & 1) * BUF_BYTES, mt, nb, q, c, slSel);
    }
    __syncthreads();

    // ---- gather XF rows via cp.async ----
    #pragma unroll
    for (int rr = 0; rr < 8; ++rr) {
        const int row = wid * 8 + rr;
        const char* src = (const char*)(XF + (size_t)sRow[row] * 256);
        cp16(sbase + (uint32_t)(row * 1040) + lane * 16,       src + lane * 16);
        cp16(sbase + (uint32_t)(row * 1040) + 512 + lane * 16, src + 512 + lane * 16);
    }
    CP_COMMIT();
    CP_WAIT0();
    __syncthreads();

    // ---- epilogue ----
    #pragma unroll
    for (int nt = 0; nt < 8; ++nt) {
        const int col = nb * 64 + nt * 8 + 2 * c;
        float2 bv = *(const float2*)(b2 + col);
        float pe = 0.0f, po = 0.0f;
        #pragma unroll
        for (int t = 0; t < 2; ++t) {
            #pragma unroll
            for (int p = 0; p < 2; ++p) {
                const int row = mt * 32 + t * 16 + q + 8 * p;
                const float m = sM[row];
                float2 x = *(const float2*)(sX + row * SXS + col);
                pe = fmaf(m * (acc[t][nt][2 * p]     + bv.x), x.x, pe);
                po = fmaf(m * (acc[t][nt][2 * p + 1] + bv.y), x.y, po);
            }
        }
        pe += __shfl_xor_sync(0xffffffffu, pe, 4);
        pe += __shfl_xor_sync(0xffffffffu, pe, 8);
        pe += __shfl_xor_sync(0xffffffffu, pe, 16);
        po += __shfl_xor_sync(0xffffffffu, po, 4);
        po += __shfl_xor_sync(0xffffffffu, po, 8);
        po += __shfl_xor_sync(0xffffffffu, po, 16);
        if (q == nt) {
            sRed[mt * 256 + col]     = pe;
            sRed[mt * 256 + col + 1] = po;
        }
    }
    __syncthreads();
    Y[(size_t)bid * 256 + tid] = sRed[tid] + sRed[256 + tid];
}

// ================= K1: XF = x @ W_in2f (HMMA, M=32/CTA) =================

__global__ __launch_bounds__(BDIM)
void k1_hmma(const float* __restrict__ x, const uint4* __restrict__ wis,
             float* __restrict__ XF)
{
    extern __shared__ char smc[];
    float* sX = (float*)smc;
    const uint32_t sbase = smem_u32(smc);
    const int tid = threadIdx.x, wid = tid >> 5, lane = tid & 31;
    const int q = lane >> 2, c = lane & 3;
    const int slSel = (c + (q >> 1)) & 3;
    const int nb = wid;
    const int bid = blockIdx.x;

    stage_at(sbase + K1_SLOT_OFF, wis, 0, tid);
    {   // x rows [bid*32..+31], 256 cols, via cp.async (rows 1024B contiguous)
        const char* xg = (const char*)(x + (size_t)bid * 8192);
        #pragma unroll
        for (int u = 0; u < 8; ++u) {
            int unit = tid + u * 256;           // 0..2047
            int row = unit >> 6, c16 = unit & 63;
            cp16(sbase + (uint32_t)(row * 1040 + c16 * 16), xg + unit * 16);
        }
    }
    CP_COMMIT();

    float acc[2][4][4];
    #pragma unroll
    for (int a = 0; a < 2; ++a)
        #pragma unroll
        for (int n = 0; n < 4; ++n)
            #pragma unroll
            for (int i = 0; i < 4; ++i) acc[a][n][i] = 0.0f;

    #pragma unroll 1
    for (int s = 0; s < 16; ++s) {
        CP_WAIT0();
        __syncthreads();
        if (s < 15) { stage_at(sbase + K1_SLOT_OFF + ((s + 1) & 1) * BUF_BYTES, wis, s + 1, tid); CP_COMMIT(); }
        gemm_kstep32(acc, sX, 0, s * 16, smc + K1_SLOT_OFF + (s & 1) * BUF_BYTES, nb, q, c, slSel);
    }
    __syncthreads();

    #pragma unroll
    for (int nt = 0; nt < 4; ++nt) {
        const int col = nb * 32 + nt * 8 + 2 * c;
        #pragma unroll
        for (int t = 0; t < 2; ++t) {
            const int r0 = t * 16 + q;
            *(float2*)(sX + r0 * SXS + col)       = make_float2(acc[t][nt][0], acc[t][nt][1]);
            *(float2*)(sX + (r0 + 8) * SXS + col) = make_float2(acc[t][nt][2], acc[t][nt][3]);
        }
    }
    __syncthreads();
    {
        float4* dst = (float4*)(XF + (size_t)bid * 8192);
        #pragma unroll
        for (int u = 0; u < 8; ++u) {
            int i4 = tid + u * 256;
            int row = i4 >> 6, c4 = i4 & 63;
            dst[i4] = *(const float4*)(sX + row * SXS + c4 * 4);
        }
    }
}

// ================= K3: tail (HMMA, M=32/CTA) =================

__global__ __launch_bounds__(BDIM)
void tail_hmma(const float* __restrict__ Yin, const float* __restrict__ Gin,
               const uint4* __restrict__ wfs, const float* __restrict__ bf,
               const uint4* __restrict__ wdg, const float* __restrict__ bd,
               float* __restrict__ out)
{
    extern __shared__ char smc[];
    float* sX = (float*)smc;
    const uint32_t sbase = smem_u32(smc);
    const int tid = threadIdx.x, wid = tid >> 5, lane = tid & 31;
    const int q = lane >> 2, c = lane & 3;
    const int slSel = (c + (q >> 1)) & 3;
    const int nb = wid;
    const int bid = blockIdx.x;

    stage_at(sbase + T_SLOT_OFF, wfs, 0, tid);
    {   // Y rows -> sX rows 0..31; G rows -> sX rows 32..63 (cols 0..127)
        const char* yg = (const char*)(Yin + (size_t)bid * 8192);
        #pragma unroll
        for (int u = 0; u < 8; ++u) {
            int unit = tid + u * 256;
            int row = unit >> 6, c16 = unit & 63;
            cp16(sbase + (uint32_t)(row * 1040 + c16 * 16), yg + unit * 16);
        }
        const char* gg = (const char*)(Gin + (size_t)bid * 4096);
        #pragma unroll
        for (int u = 0; u < 4; ++u) {
            int unit = tid + u * 256;
            int row = unit >> 5, c16 = unit & 31;
            cp16(sbase + (uint32_t)((32 + row) * 1040 + c16 * 16), gg + unit * 16);
        }
    }
    CP_COMMIT();

    float acc[2][4][4];
    #pragma unroll
    for (int a = 0; a < 2; ++a)
        #pragma unroll
        for (int n = 0; n < 4; ++n)
            #pragma unroll
            for (int i = 0; i < 4; ++i) acc[a][n][i] = 0.0f;

    // phase A: T = Y @ W_f2out + bf
    #pragma unroll 1
    for (int s = 0; s < 16; ++s) {
        CP_WAIT0();
        __syncthreads();
        if (s < 15) { stage_at(sbase + T_SLOT_OFF + ((s + 1) & 1) * BUF_BYTES, wfs, s + 1, tid); CP_COMMIT(); }
        gemm_kstep32(acc, sX, 0, s * 16, smc + T_SLOT_OFF + (s & 1) * BUF_BYTES, nb, q, c, slSel);
    }
    __syncthreads();

    stage_at(sbase + T_SLOT_OFF, wdg, 0, tid);
    CP_COMMIT();

    #pragma unroll
    for (int nt = 0; nt < 4; ++nt) {
        const int col = nb * 32 + nt * 8 + 2 * c;
        float2 bv = *(const float2*)(bf + col);
        #pragma unroll
        for (int t = 0; t < 2; ++t) {
            const int r0 = t * 16 + q;
            *(float2*)(sX + r0 * SXS + col) =
                make_float2(acc[t][nt][0] + bv.x, acc[t][nt][1] + bv.y);
            *(float2*)(sX + (r0 + 8) * SXS + col) =
                make_float2(acc[t][nt][2] + bv.x, acc[t][nt][3] + bv.y);
        }
    }
    #pragma unroll
    for (int a = 0; a < 2; ++a)
        #pragma unroll
        for (int n = 0; n < 4; ++n)
            #pragma unroll
            for (int i = 0; i < 4; ++i) acc[a][n][i] = 0.0f;

    // phase B: U = T @ W_dense (0..15) + G @ W_ang (16..23)
    #pragma unroll 1
    for (int s = 0; s < 24; ++s) {
        CP_WAIT0();
        __syncthreads();
        if (s < 23) { stage_at(sbase + T_SLOT_OFF + ((s + 1) & 1) * BUF_BYTES, wdg, s + 1, tid); CP_COMMIT(); }
        const int rowbase = (s < 16) ? 0 : 32;
        const int k0 = (s < 16) ? s * 16 : (s - 16) * 16;
        gemm_kstep32(acc, sX, rowbase, k0, smc + T_SLOT_OFF + (s & 1) * BUF_BYTES, nb, q, c, slSel);
    }
    __syncthreads();

    #pragma unroll
    for (int nt = 0; nt < 4; ++nt) {
        const int col = nb * 32 + nt * 8 + 2 * c;
        float2 bv = *(const float2*)(bd + col);
        #pragma unroll
        for (int t = 0; t < 2; ++t) {
            const int r0 = t * 16 + q;
            *(float2*)(sX + r0 * SXS + col) =
                make_float2(sspf(acc[t][nt][0] + bv.x), sspf(acc[t][nt][1] + bv.y));
            *(float2*)(sX + (r0 + 8) * SXS + col) =
                make_float2(sspf(acc[t][nt][2] + bv.x), sspf(acc[t][nt][3] + bv.y));
        }
    }
    __syncthreads();
    {
        float4* dst = (float4*)(out + (size_t)bid * 8192);
        #pragma unroll
        for (int u = 0; u < 8; ++u) {
            int i4 = tid + u * 256;
            int row = i4 >> 6, c4 = i4 & 63;
            dst[i4] = *(const float4*)(sX + row * SXS + c4 * 4);
        }
    }
}

// ---------------------------------------------------------------------------

extern "C" void kernel_launch(void* const* d_in, const int* in_sizes, int n_in,
                              void* d_out, int out_size)
{
    const float* x        = (const float*)d_in[0];
    const float* r_ij     = (const float*)d_in[1];
    const float* f_ij     = (const float*)d_in[2];
    const float* G_i      = (const float*)d_in[3];
    const float* nmask    = (const float*)d_in[4];
    const int*   neigh    = (const int*)  d_in[5];
    const float* W_in2f   = (const float*)d_in[6];
    const float* W1       = (const float*)d_in[7];
    const float* b1       = (const float*)d_in[8];
    const float* W2       = (const float*)d_in[9];
    const float* b2       = (const float*)d_in[10];
    const float* W_f2out  = (const float*)d_in[11];
    const float* b_f2out  = (const float*)d_in[12];
    const float* W_dense  = (const float*)d_in[13];
    const float* b_dense  = (const float*)d_in[14];
    const float* W_ang    = (const float*)d_in[15];
    float* out = (float*)d_out;

    float *pXF, *pY;
    uint4 *p1s, *p2s, *pis, *pfs, *pdg;
    cudaGetSymbolAddress((void**)&pXF, g_XF);
    cudaGetSymbolAddress((void**)&pY,  g_Y);
    cudaGetSymbolAddress((void**)&p1s, g_w1s);
    cudaGetSymbolAddress((void**)&p2s, g_w2s);
    cudaGetSymbolAddress((void**)&pis, g_wis);
    cudaGetSymbolAddress((void**)&pfs, g_wfs);
    cudaGetSymbolAddress((void**)&pdg, g_wdg);

    cudaFuncSetAttribute(k1_hmma,   cudaFuncAttributeMaxDynamicSharedMemorySize, SMEM_K1_TOTAL);
    cudaFuncSetAttribute(k2_hmma,   cudaFuncAttributeMaxDynamicSharedMemorySize, SMEM_K2_TOTAL);
    cudaFuncSetAttribute(tail_hmma, cudaFuncAttributeMaxDynamicSharedMemorySize, SMEM_T_TOTAL);

    prep_all<<<320, 256>>>(W1, W2, W_in2f, W_f2out, W_dense, W_ang,
                           p1s, p2s, pis, pfs, pdg);
    k1_hmma<<<NATOMS / 32, BDIM, SMEM_K1_TOTAL>>>(x, pis, pXF);
    k2_hmma<<<NATOMS, BDIM, SMEM_K2_TOTAL>>>(
        f_ij, r_ij, nmask, neigh, p1s, p2s, b1, b2, pXF, pY);
    tail_hmma<<<NATOMS / 32, BDIM, SMEM_T_TOTAL>>>(
        pY, G_i, pfs, b_f2out, pdg, b_dense, out);
}